// round 9
// baseline (speedup 1.0000x reference)
#include <cuda_runtime.h>
#include <cuda_pipeline.h>
#include <math.h>

// ---------------- problem constants ----------------
#define BATCH 2
#define SEQ   2048
#define DIM   1024
#define NHEAD 16
#define HDIM  64
#define ROWS  (BATCH*SEQ)          // 4096
#define D3    (3*DIM)              // 3072
#define D4    (4*DIM)              // 4096
#define NTILE 32                   // SEQ/64 k-tiles

// tf32 GEMM smem strides (floats); conflict-free fragment LDS.
#define AST 36
#define WST 136
#define ASZ (128*AST)
#define WSZ (32*WST)

// attention smem strides
#define QS 68   // 68 % 32 == 4  -> conflict-free for row-indexed frags
#define VS 72   // 72 % 32 == 8  -> conflict-free for k-indexed frags

// ---------------- scratch (static device memory; 16B aligned) ---------------
__device__ __align__(16) float g_h1  [(size_t)ROWS*DIM];
__device__ __align__(16) float g_qkv [(size_t)ROWS*D3];
__device__ __align__(16) float g_attn[(size_t)ROWS*DIM];
__device__ __align__(16) float g_x1  [(size_t)ROWS*DIM];
__device__ __align__(16) float g_h2  [(size_t)ROWS*DIM];
__device__ __align__(16) float g_fc  [(size_t)ROWS*D4];
// tf32-rounded weight copies
__device__ __align__(16) float g_wq [(size_t)DIM*D3];
__device__ __align__(16) float g_wo [(size_t)DIM*DIM];
__device__ __align__(16) float g_wf [(size_t)DIM*D4];
__device__ __align__(16) float g_wp [(size_t)D4*DIM];
// V per-tile colsums and suffix sums: [b][tile][d]
__device__ __align__(16) float g_vtile[(size_t)BATCH*NTILE*DIM];
__device__ __align__(16) float g_vsuf [(size_t)BATCH*(NTILE+1)*DIM];

// ---------------- helpers ----------------
__device__ __forceinline__ float f2tff(float x) {
    uint32_t r;
    asm("cvt.rna.tf32.f32 %0, %1;" : "=r"(r) : "f"(x));
    return __uint_as_float(r);
}

__device__ __forceinline__ void mma_tf32(float* c, const uint32_t* a, const uint32_t* b) {
    asm volatile(
        "mma.sync.aligned.m16n8k8.row.col.f32.tf32.tf32.f32 "
        "{%0,%1,%2,%3}, {%4,%5,%6,%7}, {%8,%9}, {%0,%1,%2,%3};"
        : "+f"(c[0]), "+f"(c[1]), "+f"(c[2]), "+f"(c[3])
        : "r"(a[0]), "r"(a[1]), "r"(a[2]), "r"(a[3]), "r"(b[0]), "r"(b[1]));
}

// exp via deg-7 Taylor (FMA pipe, no MUFU). |x| <~ 0.3 by construction.
__device__ __forceinline__ float exp_small(float x) {
    float p = fmaf(x, 1.f/5040.f, 1.f/720.f);
    p = fmaf(p, x, 1.f/120.f);
    p = fmaf(p, x, 1.f/24.f);
    p = fmaf(p, x, 1.f/6.f);
    p = fmaf(p, x, 0.5f);
    p = fmaf(p, x, 1.0f);
    p = fmaf(p, x, 1.0f);
    return p;
}

__device__ __forceinline__ float blockSum256(float v, float* s) {
    int lane = threadIdx.x & 31, w = threadIdx.x >> 5;
    #pragma unroll
    for (int o = 16; o; o >>= 1) v += __shfl_down_sync(0xffffffffu, v, o);
    if (!lane) s[w] = v;
    __syncthreads();
    if (threadIdx.x == 0) {
        float t = 0.f;
        #pragma unroll
        for (int i = 0; i < 8; i++) t += s[i];
        s[8] = t;
    }
    __syncthreads();
    float r = s[8];
    __syncthreads();
    return r;
}

// ---------------- tf32 pre-round (weights) ----------------
__global__ void round_tf32_kernel(const float4* __restrict__ src,
                                  float4* __restrict__ dst, int n4)
{
    int i = blockIdx.x * blockDim.x + threadIdx.x;
    if (i < n4) {
        float4 v = src[i];
        v.x = f2tff(v.x); v.y = f2tff(v.y); v.z = f2tff(v.z); v.w = f2tff(v.w);
        dst[i] = v;
    }
}

// ---------------- V per-tile column sums (coalesced) -------------------------
// grid: (BATCH*NTILE), block 256. qkv V rows are contiguous 1024 floats.
__global__ void vtile_kernel(const float* __restrict__ qkv)
{
    const int b = blockIdx.x >> 5, kt = blockIdx.x & 31;
    const int k0 = kt * 64;
    float s[4] = {0.f, 0.f, 0.f, 0.f};
    const float* vg = qkv + ((size_t)(b * SEQ + k0)) * D3 + 2 * DIM;
    for (int r = 0; r < 64; r++) {
        const float* row = vg + (size_t)r * D3;
        #pragma unroll
        for (int l = 0; l < 4; l++) s[l] += row[threadIdx.x + l * 256];
    }
    float* o = g_vtile + ((size_t)(b * NTILE + kt)) * DIM;
    #pragma unroll
    for (int l = 0; l < 4; l++) o[threadIdx.x + l * 256] = s[l];
}

// suffix scan over tiles: g_vsuf[b][t][d] = sum_{kt>=t} g_vtile[b][kt][d]
__global__ void vsuf_kernel()
{
    const int b = blockIdx.x;
    const int d = threadIdx.x + blockIdx.y * 1024;
    float acc = 0.f;
    g_vsuf[((size_t)b * (NTILE + 1) + NTILE) * DIM + d] = 0.f;
    for (int t = NTILE - 1; t >= 0; t--) {
        acc += g_vtile[((size_t)b * NTILE + t) * DIM + d];
        g_vsuf[((size_t)b * (NTILE + 1) + t) * DIM + d] = acc;
    }
}

// ---------------- LayerNorm (output tf32-rounded) ----------
__global__ void ln_kernel(const float* __restrict__ x, const float* __restrict__ w,
                          const float* __restrict__ b, float* __restrict__ y)
{
    __shared__ float red[9];
    const int row = blockIdx.x;
    const float* xr = x + (size_t)row * DIM;
    float v[4];
    #pragma unroll
    for (int l = 0; l < 4; l++) v[l] = xr[threadIdx.x + l * 256];
    float s = v[0] + v[1] + v[2] + v[3];
    const float mean = blockSum256(s, red) * (1.0f / DIM);
    float q = 0.f;
    #pragma unroll
    for (int l = 0; l < 4; l++) { float d = v[l] - mean; q += d * d; }
    const float ssq = blockSum256(q, red);
    const float stdv = sqrtf(ssq * (1.0f / (DIM - 1)));
    const float inv = 1.0f / (stdv + 1e-5f);
    float* yr = y + (size_t)row * DIM;
    #pragma unroll
    for (int l = 0; l < 4; l++) {
        int c = threadIdx.x + l * 256;
        yr[c] = f2tff(w[c] * (v[l] - mean) * inv + b[c]);
    }
}

// ---------------- tf32 tensor-core GEMM (operands pre-rounded) ---------------
__global__ void __launch_bounds__(256, 2)
gemm_tf32_kernel(const float* __restrict__ A, const float* __restrict__ W,
                 const float* __restrict__ bias, const float* __restrict__ R,
                 float* __restrict__ C, int M, int N, int K, int doGelu,
                 int roundOut)
{
    extern __shared__ float sh[];
    float* AsB = sh;              // [2][128][AST]
    float* WsB = sh + 2 * ASZ;    // [2][32][WST]

    const int tid  = threadIdx.x;
    const int lane = tid & 31, wid = tid >> 5;
    const int gid  = lane >> 2, ctg = lane & 3;
    const int wm0  = (wid >> 2) * 64;
    const int wn0  = (wid & 3) * 32;
    const int m0 = blockIdx.y << 7, n0 = blockIdx.x << 7;

    const float* Ag = A + (size_t)m0 * K;
    const float* Wg = W + n0;

    float acc[4][4][4];
    #pragma unroll
    for (int mt = 0; mt < 4; mt++)
        #pragma unroll
        for (int nt = 0; nt < 4; nt++)
            #pragma unroll
            for (int r = 0; r < 4; r++) acc[mt][nt][r] = 0.f;

    const int NIT = K >> 5;

    {
        float* Ad = AsB;
        float* Wd = WsB;
        #pragma unroll
        for (int i = 0; i < 4; i++) {
            int f = tid + i * 256;
            int row = f >> 3, kq = (f & 7) << 2;
            __pipeline_memcpy_async(Ad + row * AST + kq,
                                    Ag + (size_t)row * K + kq, 16);
            int kr = f >> 5, nq = (f & 31) << 2;
            __pipeline_memcpy_async(Wd + kr * WST + nq,
                                    Wg + (size_t)kr * N + nq, 16);
        }
    }
    __pipeline_commit();

    for (int it = 0; it < NIT; it++) {
        if (it + 1 < NIT) {
            const int k0 = (it + 1) << 5;
            float* Ad = AsB + ((it + 1) & 1) * ASZ;
            float* Wd = WsB + ((it + 1) & 1) * WSZ;
            #pragma unroll
            for (int i = 0; i < 4; i++) {
                int f = tid + i * 256;
                int row = f >> 3, kq = (f & 7) << 2;
                __pipeline_memcpy_async(Ad + row * AST + kq,
                                        Ag + (size_t)row * K + k0 + kq, 16);
                int kr = f >> 5, nq = (f & 31) << 2;
                __pipeline_memcpy_async(Wd + kr * WST + nq,
                                        Wg + (size_t)(k0 + kr) * N + nq, 16);
            }
        }
        __pipeline_commit();
        __pipeline_wait_prior(1);
        __syncthreads();

        const float* Ab = AsB + (it & 1) * ASZ;
        const float* Bb = WsB + (it & 1) * WSZ;
        #pragma unroll
        for (int ks = 0; ks < 4; ks++) {
            const int kb = ks << 3;
            uint32_t af[4][4];
            #pragma unroll
            for (int mt = 0; mt < 4; mt++) {
                const float* p = Ab + (wm0 + mt * 16 + gid) * AST + kb + ctg;
                af[mt][0] = __float_as_uint(p[0]);
                af[mt][2] = __float_as_uint(p[4]);
                af[mt][1] = __float_as_uint(p[8 * AST]);
                af[mt][3] = __float_as_uint(p[8 * AST + 4]);
            }
            uint32_t bf[4][2];
            #pragma unroll
            for (int nt = 0; nt < 4; nt++) {
                const float* p = Bb + (kb + ctg) * WST + wn0 + nt * 8 + gid;
                bf[nt][0] = __float_as_uint(p[0]);
                bf[nt][1] = __float_as_uint(p[4 * WST]);
            }
            #pragma unroll
            for (int mt = 0; mt < 4; mt++)
                #pragma unroll
                for (int nt = 0; nt < 4; nt++)
                    mma_tf32(acc[mt][nt], af[mt], bf[nt]);
        }
        __syncthreads();
    }

    #pragma unroll
    for (int mt = 0; mt < 4; mt++) {
        #pragma unroll
        for (int half = 0; half < 2; half++) {
            const int row = m0 + wm0 + mt * 16 + gid + half * 8;
            #pragma unroll
            for (int nt = 0; nt < 4; nt++) {
                const int col = n0 + wn0 + nt * 8 + 2 * ctg;
                float v0 = acc[mt][nt][half * 2 + 0] + bias[col];
                float v1 = acc[mt][nt][half * 2 + 1] + bias[col + 1];
                if (doGelu) {
                    float u = v0;
                    v0 = 0.5f * u * (1.0f + tanhf(0.7978845608028654f * (u + 0.044715f * u * u * u)));
                    u = v1;
                    v1 = 0.5f * u * (1.0f + tanhf(0.7978845608028654f * (u + 0.044715f * u * u * u)));
                }
                if (R) {
                    float2 rv = *(const float2*)(R + (size_t)row * N + col);
                    v0 += rv.x; v1 += rv.y;
                }
                if (roundOut) { v0 = f2tff(v0); v1 = f2tff(v1); }
                float2 o; o.x = v0; o.y = v1;
                *(float2*)(C + (size_t)row * N + col) = o;
            }
        }
    }
}

// ---------------- tensor-core attention (double-buffered K/V) ----------------
// Q-tile 128 rows, K-tile 64 keys, 8 warps. Masked tiles come from g_vsuf.
__global__ void __launch_bounds__(256, 1)
attn_tc_kernel(const float* __restrict__ qkv, const int* __restrict__ rel,
               const float* __restrict__ rel_emb, float* __restrict__ out)
{
    extern __shared__ float sm[];
    float* Qs = sm;                    // [128][QS]
    float* Ks = Qs + 128 * QS;         // [2][64][QS]
    float* Vs = Ks + 2 * 64 * QS;      // [2][64][VS]
    float* Ps = Vs + 2 * 64 * VS;      // [128][QS]
    float* rE = Ps + 128 * QS;         // [64]
    float* cs = rE + 64;               // [64]

    const int b = blockIdx.x >> 4, h = blockIdx.x & 15;
    const int qt = (int)gridDim.y - 1 - (int)blockIdx.y;   // heavy blocks first
    const int q0 = qt * 128;
    const int tid = threadIdx.x;
    const int lane = tid & 31, wid = tid >> 5;
    const int gid = lane >> 2, ctg = lane & 3;
    const int wrow = wid * 16;

    const int nTA = 2 * qt + 2;           // phase-A k-tiles
    const int nB  = NTILE - nTA;

    if (tid < 64) {
        rE[tid] = rel_emb[tid * NHEAD + h];
        cs[tid] = g_vsuf[((size_t)b * (NTILE + 1) + nTA) * DIM + h * HDIM + tid];
    }

    // load Q tile [128][64]
    {
        const size_t baseQ = ((size_t)(b * SEQ + q0)) * D3 + h * HDIM;
        #pragma unroll
        for (int l = 0; l < 8; l++) {
            int e = tid + l * 256;
            int row = e >> 4, cq = (e & 15) << 2;
            float4 v = *(const float4*)(qkv + baseQ + (size_t)row * D3 + cq);
            *(float4*)(Qs + row * QS + cq) = v;
        }
    }

    // cp.async K/V tile loader
    auto loadKV = [&](int kt, int buf) {
        const size_t baseK = ((size_t)(b * SEQ + kt * 64)) * D3 + DIM + h * HDIM;
        float* Kd = Ks + buf * 64 * QS;
        float* Vd = Vs + buf * 64 * VS;
        #pragma unroll
        for (int l = 0; l < 4; l++) {
            int e = tid + l * 256;
            int row = e >> 4, cq = (e & 15) << 2;
            __pipeline_memcpy_async(Kd + row * QS + cq,
                                    qkv + baseK + (size_t)row * D3 + cq, 16);
            __pipeline_memcpy_async(Vd + row * VS + cq,
                                    qkv + baseK + DIM + (size_t)row * D3 + cq, 16);
        }
        __pipeline_commit();
    };

    float o[8][4];
    #pragma unroll
    for (int nt = 0; nt < 8; nt++)
        #pragma unroll
        for (int r = 0; r < 4; r++) o[nt][r] = 0.f;
    float dacc0 = 0.f, dacc1 = 0.f;

    const int qg0 = q0 + wrow + gid, qg1 = qg0 + 8;
    const int* relr0 = rel + ((size_t)b * SEQ + qg0) * SEQ;
    const int* relr1 = rel + ((size_t)b * SEQ + qg1) * SEQ;

    loadKV(0, 0);

    for (int kt = 0; kt < nTA; kt++) {
        const int k0 = kt * 64;
        const int buf = kt & 1;
        if (kt + 1 < nTA) {
            loadKV(kt + 1, buf ^ 1);
            __pipeline_wait_prior(1);
        } else {
            __pipeline_wait_prior(0);
        }
        __syncthreads();

        const float* Kb = Ks + buf * 64 * QS;
        const float* Vb = Vs + buf * 64 * VS;

        // S = Q K^T
        float s[8][4];
        #pragma unroll
        for (int nt = 0; nt < 8; nt++)
            #pragma unroll
            for (int r = 0; r < 4; r++) s[nt][r] = 0.f;
        #pragma unroll
        for (int ks = 0; ks < 8; ks++) {
            const int kb = ks << 3;
            uint32_t a[4];
            const float* ap = Qs + (wrow + gid) * QS + kb + ctg;
            a[0] = __float_as_uint(ap[0]);
            a[1] = __float_as_uint(ap[8 * QS]);
            a[2] = __float_as_uint(ap[4]);
            a[3] = __float_as_uint(ap[8 * QS + 4]);
            #pragma unroll
            for (int nt = 0; nt < 8; nt++) {
                uint32_t bb[2];
                const float* bp = Kb + (nt * 8 + gid) * QS + kb + ctg;
                bb[0] = __float_as_uint(bp[0]);
                bb[1] = __float_as_uint(bp[4]);
                mma_tf32(s[nt], a, bb);
            }
        }

        // p = exp(s * 0.125 * rel_emb[rel]) for k<=q else 1
        #pragma unroll
        for (int nt = 0; nt < 8; nt++) {
            const int kg = k0 + nt * 8 + 2 * ctg;
            int2 r0 = *(const int2*)(relr0 + kg);
            int2 r1 = *(const int2*)(relr1 + kg);
            float p00 = (kg     <= qg0) ? exp_small(s[nt][0] * 0.125f * rE[r0.x]) : 1.0f;
            float p01 = (kg + 1 <= qg0) ? exp_small(s[nt][1] * 0.125f * rE[r0.y]) : 1.0f;
            float p10 = (kg     <= qg1) ? exp_small(s[nt][2] * 0.125f * rE[r1.x]) : 1.0f;
            float p11 = (kg + 1 <= qg1) ? exp_small(s[nt][3] * 0.125f * rE[r1.y]) : 1.0f;
            dacc0 += p00 + p01;
            dacc1 += p10 + p11;
            float2 w0; w0.x = f2tff(p00); w0.y = f2tff(p01);
            float2 w1; w1.x = f2tff(p10); w1.y = f2tff(p11);
            *(float2*)(Ps + (wrow + gid) * QS + nt * 8 + 2 * ctg) = w0;
            *(float2*)(Ps + (wrow + 8 + gid) * QS + nt * 8 + 2 * ctg) = w1;
        }
        __syncwarp();

        // O += P V   (each warp reads only its own 16 Ps rows)
        #pragma unroll
        for (int ks = 0; ks < 8; ks++) {
            const int kb = ks << 3;
            uint32_t a[4];
            const float* ap = Ps + (wrow + gid) * QS + kb + ctg;
            a[0] = __float_as_uint(ap[0]);
            a[1] = __float_as_uint(ap[8 * QS]);
            a[2] = __float_as_uint(ap[4]);
            a[3] = __float_as_uint(ap[8 * QS + 4]);
            #pragma unroll
            for (int nt = 0; nt < 8; nt++) {
                uint32_t bb[2];
                const float* bp = Vb + (kb + ctg) * VS + nt * 8 + gid;
                bb[0] = __float_as_uint(bp[0]);
                bb[1] = __float_as_uint(bp[4 * VS]);
                mma_tf32(o[nt], a, bb);
            }
        }
        __syncthreads();   // all warps done with buf before it is overwritten
    }

    // row denominators: reduce dacc over the 4 ctg lanes, add masked count
    dacc0 += __shfl_xor_sync(0xffffffffu, dacc0, 1);
    dacc0 += __shfl_xor_sync(0xffffffffu, dacc0, 2);
    dacc1 += __shfl_xor_sync(0xffffffffu, dacc1, 1);
    dacc1 += __shfl_xor_sync(0xffffffffu, dacc1, 2);
    const float i0 = 1.0f / (dacc0 + 64.0f * (float)nB);
    const float i1 = 1.0f / (dacc1 + 64.0f * (float)nB);

    float* o0 = out + ((size_t)b * SEQ + qg0) * DIM + h * HDIM;
    float* o1 = out + ((size_t)b * SEQ + qg1) * DIM + h * HDIM;
    #pragma unroll
    for (int nt = 0; nt < 8; nt++) {
        const int c = nt * 8 + 2 * ctg;
        const float cs0 = cs[c], cs1 = cs[c + 1];
        float2 w0, w1;
        w0.x = f2tff((o[nt][0] + cs0) * i0);
        w0.y = f2tff((o[nt][1] + cs1) * i0);
        w1.x = f2tff((o[nt][2] + cs0) * i1);
        w1.y = f2tff((o[nt][3] + cs1) * i1);
        *(float2*)(o0 + c) = w0;
        *(float2*)(o1 + c) = w1;
    }
}

// ---------------- launcher ----------------
extern "C" void kernel_launch(void* const* d_in, const int* in_sizes, int n_in,
                              void* d_out, int out_size)
{
    const float* x     = (const float*)d_in[0];
    const int*   rel   = (const int*)  d_in[1];
    const float* ln1w  = (const float*)d_in[2];
    const float* ln1b  = (const float*)d_in[3];
    const float* Wqkv  = (const float*)d_in[4];
    const float* bqkv  = (const float*)d_in[5];
    const float* Wo    = (const float*)d_in[6];
    const float* bo    = (const float*)d_in[7];
    const float* rele  = (const float*)d_in[8];
    const float* ln2w  = (const float*)d_in[9];
    const float* ln2b  = (const float*)d_in[10];
    const float* Wfc   = (const float*)d_in[11];
    const float* bfc   = (const float*)d_in[12];
    const float* Wp    = (const float*)d_in[13];
    const float* bp    = (const float*)d_in[14];
    float* out = (float*)d_out;

    float *h1, *qkv, *attn, *x1, *h2, *fc, *wq, *wo, *wf, *wp;
    cudaGetSymbolAddress((void**)&h1,   g_h1);
    cudaGetSymbolAddress((void**)&qkv,  g_qkv);
    cudaGetSymbolAddress((void**)&attn, g_attn);
    cudaGetSymbolAddress((void**)&x1,   g_x1);
    cudaGetSymbolAddress((void**)&h2,   g_h2);
    cudaGetSymbolAddress((void**)&fc,   g_fc);
    cudaGetSymbolAddress((void**)&wq,   g_wq);
    cudaGetSymbolAddress((void**)&wo,   g_wo);
    cudaGetSymbolAddress((void**)&wf,   g_wf);
    cudaGetSymbolAddress((void**)&wp,   g_wp);

    const int gemmSmem = (2 * ASZ + 2 * WSZ) * (int)sizeof(float);
    cudaFuncSetAttribute(gemm_tf32_kernel,
                         cudaFuncAttributeMaxDynamicSharedMemorySize, gemmSmem);
    const int attnSmem = (128*QS + 2*64*QS + 2*64*VS + 128*QS + 64 + 64)
                         * (int)sizeof(float);
    cudaFuncSetAttribute(attn_tc_kernel,
                         cudaFuncAttributeMaxDynamicSharedMemorySize, attnSmem);

    // 0. pre-round weights to tf32
    {
        int n;
        n = DIM*D3/4;  round_tf32_kernel<<<(n+255)/256, 256>>>((const float4*)Wqkv, (float4*)wq, n);
        n = DIM*DIM/4; round_tf32_kernel<<<(n+255)/256, 256>>>((const float4*)Wo,   (float4*)wo, n);
        n = DIM*D4/4;  round_tf32_kernel<<<(n+255)/256, 256>>>((const float4*)Wfc,  (float4*)wf, n);
        n = D4*DIM/4;  round_tf32_kernel<<<(n+255)/256, 256>>>((const float4*)Wp,   (float4*)wp, n);
    }

    // 1. LN1 (tf32-rounded out)
    ln_kernel<<<ROWS, 256>>>(x, ln1w, ln1b, h1);
    // 2. QKV GEMM (rounded out: feeds attention MMA)
    gemm_tf32_kernel<<<dim3(D3/128, ROWS/128), 256, gemmSmem>>>(h1, wq, bqkv, nullptr, qkv,
                                                                ROWS, D3, DIM, 0, 1);
    // 2b. V tile colsums + suffix scan (for fully-masked attention tiles)
    vtile_kernel<<<BATCH*NTILE, 256>>>(qkv);
    vsuf_kernel<<<dim3(BATCH, 1), 1024>>>();
    // 3. Attention (tensor-core; rounded out: feeds Wo)
    attn_tc_kernel<<<dim3(BATCH*NHEAD, SEQ/128), 256, attnSmem>>>(qkv, rel, rele, attn);
    // 4. Wo + residual(x) -> x1 (fp32)
    gemm_tf32_kernel<<<dim3(DIM/128, ROWS/128), 256, gemmSmem>>>(attn, wo, bo, x, x1,
                                                                 ROWS, DIM, DIM, 0, 0);
    // 5. LN2 (rounded out)
    ln_kernel<<<ROWS, 256>>>(x1, ln2w, ln2b, h2);
    // 6. FC + GELU (rounded out: feeds Wp)
    gemm_tf32_kernel<<<dim3(D4/128, ROWS/128), 256, gemmSmem>>>(h2, wf, bfc, nullptr, fc,
                                                                ROWS, D4, DIM, 1, 1);
    // 7. Wp + residual(x1) -> out (fp32)
    gemm_tf32_kernel<<<dim3(DIM/128, ROWS/128), 256, gemmSmem>>>(fc, wp, bp, x1, out,
                                                                 ROWS, DIM, D4, 0, 0);
}

// round 10
// speedup vs baseline: 1.5028x; 1.5028x over previous
#include <cuda_runtime.h>
#include <cuda_pipeline.h>
#include <math.h>

// ---------------- problem constants ----------------
#define BATCH 2
#define SEQ   2048
#define DIM   1024
#define NHEAD 16
#define HDIM  64
#define ROWS  (BATCH*SEQ)          // 4096
#define D3    (3*DIM)              // 3072
#define D4    (4*DIM)              // 4096
#define NTILE 32                   // SEQ/64 k-tiles

// tf32 GEMM smem strides (floats); conflict-free fragment LDS.
#define AST 36
#define WST 136
#define ASZ (128*AST)
#define WSZ (32*WST)

// attention smem strides
#define QS 68   // 68 % 32 == 4  -> conflict-free for row-indexed frags
#define VS 72   // 72 % 32 == 8  -> conflict-free for k-indexed frags

// ---------------- scratch (static device memory; 16B aligned) ---------------
__device__ __align__(16) float g_h1  [(size_t)ROWS*DIM];
__device__ __align__(16) float g_qkv [(size_t)ROWS*D3];
__device__ __align__(16) float g_attn[(size_t)ROWS*DIM];
__device__ __align__(16) float g_x1  [(size_t)ROWS*DIM];
__device__ __align__(16) float g_h2  [(size_t)ROWS*DIM];
__device__ __align__(16) float g_fc  [(size_t)ROWS*D4];
// tf32-rounded weight copies
__device__ __align__(16) float g_wq [(size_t)DIM*D3];
__device__ __align__(16) float g_wo [(size_t)DIM*DIM];
__device__ __align__(16) float g_wf [(size_t)DIM*D4];
__device__ __align__(16) float g_wp [(size_t)D4*DIM];
// V per-tile colsums and suffix sums: [b][tile][d]
__device__ __align__(16) float g_vtile[(size_t)BATCH*NTILE*DIM];
__device__ __align__(16) float g_vsuf [(size_t)BATCH*(NTILE+1)*DIM];

// ---------------- helpers ----------------
__device__ __forceinline__ float f2tff(float x) {
    uint32_t r;
    asm("cvt.rna.tf32.f32 %0, %1;" : "=r"(r) : "f"(x));
    return __uint_as_float(r);
}

__device__ __forceinline__ void mma_tf32(float* c, const uint32_t* a, const uint32_t* b) {
    asm volatile(
        "mma.sync.aligned.m16n8k8.row.col.f32.tf32.tf32.f32 "
        "{%0,%1,%2,%3}, {%4,%5,%6,%7}, {%8,%9}, {%0,%1,%2,%3};"
        : "+f"(c[0]), "+f"(c[1]), "+f"(c[2]), "+f"(c[3])
        : "r"(a[0]), "r"(a[1]), "r"(a[2]), "r"(a[3]), "r"(b[0]), "r"(b[1]));
}

// exp via deg-7 Taylor (FMA pipe, no MUFU). |x| <~ 0.3 by construction.
__device__ __forceinline__ float exp_small(float x) {
    float p = fmaf(x, 1.f/5040.f, 1.f/720.f);
    p = fmaf(p, x, 1.f/120.f);
    p = fmaf(p, x, 1.f/24.f);
    p = fmaf(p, x, 1.f/6.f);
    p = fmaf(p, x, 0.5f);
    p = fmaf(p, x, 1.0f);
    p = fmaf(p, x, 1.0f);
    return p;
}

__device__ __forceinline__ float blockSum256(float v, float* s) {
    int lane = threadIdx.x & 31, w = threadIdx.x >> 5;
    #pragma unroll
    for (int o = 16; o; o >>= 1) v += __shfl_down_sync(0xffffffffu, v, o);
    if (!lane) s[w] = v;
    __syncthreads();
    if (threadIdx.x == 0) {
        float t = 0.f;
        #pragma unroll
        for (int i = 0; i < 8; i++) t += s[i];
        s[8] = t;
    }
    __syncthreads();
    float r = s[8];
    __syncthreads();
    return r;
}

// ---------------- tf32 pre-round (weights) ----------------
__global__ void round_tf32_kernel(const float4* __restrict__ src,
                                  float4* __restrict__ dst, int n4)
{
    int i = blockIdx.x * blockDim.x + threadIdx.x;
    if (i < n4) {
        float4 v = src[i];
        v.x = f2tff(v.x); v.y = f2tff(v.y); v.z = f2tff(v.z); v.w = f2tff(v.w);
        dst[i] = v;
    }
}

// ---------------- V per-tile column sums (coalesced) -------------------------
__global__ void vtile_kernel(const float* __restrict__ qkv)
{
    const int b = blockIdx.x >> 5, kt = blockIdx.x & 31;
    const int k0 = kt * 64;
    float s[4] = {0.f, 0.f, 0.f, 0.f};
    const float* vg = qkv + ((size_t)(b * SEQ + k0)) * D3 + 2 * DIM;
    for (int r = 0; r < 64; r++) {
        const float* row = vg + (size_t)r * D3;
        #pragma unroll
        for (int l = 0; l < 4; l++) s[l] += row[threadIdx.x + l * 256];
    }
    float* o = g_vtile + ((size_t)(b * NTILE + kt)) * DIM;
    #pragma unroll
    for (int l = 0; l < 4; l++) o[threadIdx.x + l * 256] = s[l];
}

// suffix scan over tiles: g_vsuf[b][t][d] = sum_{kt>=t} g_vtile[b][kt][d]
__global__ void vsuf_kernel()
{
    const int b = blockIdx.x;
    const int d = threadIdx.x;
    float acc = 0.f;
    g_vsuf[((size_t)b * (NTILE + 1) + NTILE) * DIM + d] = 0.f;
    for (int t = NTILE - 1; t >= 0; t--) {
        acc += g_vtile[((size_t)b * NTILE + t) * DIM + d];
        g_vsuf[((size_t)b * (NTILE + 1) + t) * DIM + d] = acc;
    }
}

// ---------------- LayerNorm (output tf32-rounded) ----------
__global__ void ln_kernel(const float* __restrict__ x, const float* __restrict__ w,
                          const float* __restrict__ b, float* __restrict__ y)
{
    __shared__ float red[9];
    const int row = blockIdx.x;
    const float* xr = x + (size_t)row * DIM;
    float v[4];
    #pragma unroll
    for (int l = 0; l < 4; l++) v[l] = xr[threadIdx.x + l * 256];
    float s = v[0] + v[1] + v[2] + v[3];
    const float mean = blockSum256(s, red) * (1.0f / DIM);
    float q = 0.f;
    #pragma unroll
    for (int l = 0; l < 4; l++) { float d = v[l] - mean; q += d * d; }
    const float ssq = blockSum256(q, red);
    const float stdv = sqrtf(ssq * (1.0f / (DIM - 1)));
    const float inv = 1.0f / (stdv + 1e-5f);
    float* yr = y + (size_t)row * DIM;
    #pragma unroll
    for (int l = 0; l < 4; l++) {
        int c = threadIdx.x + l * 256;
        yr[c] = f2tff(w[c] * (v[l] - mean) * inv + b[c]);
    }
}

// ---------------- tf32 tensor-core GEMM (operands pre-rounded) ---------------
__global__ void __launch_bounds__(256, 2)
gemm_tf32_kernel(const float* __restrict__ A, const float* __restrict__ W,
                 const float* __restrict__ bias, const float* __restrict__ R,
                 float* __restrict__ C, int M, int N, int K, int doGelu,
                 int roundOut)
{
    extern __shared__ float sh[];
    float* AsB = sh;              // [2][128][AST]
    float* WsB = sh + 2 * ASZ;    // [2][32][WST]

    const int tid  = threadIdx.x;
    const int lane = tid & 31, wid = tid >> 5;
    const int gid  = lane >> 2, ctg = lane & 3;
    const int wm0  = (wid >> 2) * 64;
    const int wn0  = (wid & 3) * 32;
    const int m0 = blockIdx.y << 7, n0 = blockIdx.x << 7;

    const float* Ag = A + (size_t)m0 * K;
    const float* Wg = W + n0;

    float acc[4][4][4];
    #pragma unroll
    for (int mt = 0; mt < 4; mt++)
        #pragma unroll
        for (int nt = 0; nt < 4; nt++)
            #pragma unroll
            for (int r = 0; r < 4; r++) acc[mt][nt][r] = 0.f;

    const int NIT = K >> 5;

    {
        float* Ad = AsB;
        float* Wd = WsB;
        #pragma unroll
        for (int i = 0; i < 4; i++) {
            int f = tid + i * 256;
            int row = f >> 3, kq = (f & 7) << 2;
            __pipeline_memcpy_async(Ad + row * AST + kq,
                                    Ag + (size_t)row * K + kq, 16);
            int kr = f >> 5, nq = (f & 31) << 2;
            __pipeline_memcpy_async(Wd + kr * WST + nq,
                                    Wg + (size_t)kr * N + nq, 16);
        }
    }
    __pipeline_commit();

    for (int it = 0; it < NIT; it++) {
        if (it + 1 < NIT) {
            const int k0 = (it + 1) << 5;
            float* Ad = AsB + ((it + 1) & 1) * ASZ;
            float* Wd = WsB + ((it + 1) & 1) * WSZ;
            #pragma unroll
            for (int i = 0; i < 4; i++) {
                int f = tid + i * 256;
                int row = f >> 3, kq = (f & 7) << 2;
                __pipeline_memcpy_async(Ad + row * AST + kq,
                                        Ag + (size_t)row * K + k0 + kq, 16);
                int kr = f >> 5, nq = (f & 31) << 2;
                __pipeline_memcpy_async(Wd + kr * WST + nq,
                                        Wg + (size_t)(k0 + kr) * N + nq, 16);
            }
        }
        __pipeline_commit();
        __pipeline_wait_prior(1);
        __syncthreads();

        const float* Ab = AsB + (it & 1) * ASZ;
        const float* Bb = WsB + (it & 1) * WSZ;
        #pragma unroll
        for (int ks = 0; ks < 4; ks++) {
            const int kb = ks << 3;
            uint32_t af[4][4];
            #pragma unroll
            for (int mt = 0; mt < 4; mt++) {
                const float* p = Ab + (wm0 + mt * 16 + gid) * AST + kb + ctg;
                af[mt][0] = __float_as_uint(p[0]);
                af[mt][2] = __float_as_uint(p[4]);
                af[mt][1] = __float_as_uint(p[8 * AST]);
                af[mt][3] = __float_as_uint(p[8 * AST + 4]);
            }
            uint32_t bf[4][2];
            #pragma unroll
            for (int nt = 0; nt < 4; nt++) {
                const float* p = Bb + (kb + ctg) * WST + wn0 + nt * 8 + gid;
                bf[nt][0] = __float_as_uint(p[0]);
                bf[nt][1] = __float_as_uint(p[4 * WST]);
            }
            #pragma unroll
            for (int mt = 0; mt < 4; mt++)
                #pragma unroll
                for (int nt = 0; nt < 4; nt++)
                    mma_tf32(acc[mt][nt], af[mt], bf[nt]);
        }
        __syncthreads();
    }

    #pragma unroll
    for (int mt = 0; mt < 4; mt++) {
        #pragma unroll
        for (int half = 0; half < 2; half++) {
            const int row = m0 + wm0 + mt * 16 + gid + half * 8;
            #pragma unroll
            for (int nt = 0; nt < 4; nt++) {
                const int col = n0 + wn0 + nt * 8 + 2 * ctg;
                float v0 = acc[mt][nt][half * 2 + 0] + bias[col];
                float v1 = acc[mt][nt][half * 2 + 1] + bias[col + 1];
                if (doGelu) {
                    float u = v0;
                    v0 = 0.5f * u * (1.0f + tanhf(0.7978845608028654f * (u + 0.044715f * u * u * u)));
                    u = v1;
                    v1 = 0.5f * u * (1.0f + tanhf(0.7978845608028654f * (u + 0.044715f * u * u * u)));
                }
                if (R) {
                    float2 rv = *(const float2*)(R + (size_t)row * N + col);
                    v0 += rv.x; v1 += rv.y;
                }
                if (roundOut) { v0 = f2tff(v0); v1 = f2tff(v1); }
                float2 o; o.x = v0; o.y = v1;
                *(float2*)(C + (size_t)row * N + col) = o;
            }
        }
    }
}

// ---------------- tensor-core attention (single buffer; 2 CTAs/SM) ----------
// Q-tile 128 rows, K-tile 64 keys, 8 warps. Fully-masked tiles via g_vsuf.
__global__ void __launch_bounds__(256, 1)
attn_tc_kernel(const float* __restrict__ qkv, const int* __restrict__ rel,
               const float* __restrict__ rel_emb, float* __restrict__ out)
{
    extern __shared__ float sm[];
    float* Qs = sm;                    // [128][QS]
    float* Ks = Qs + 128 * QS;         // [64][QS]
    float* Vs = Ks + 64 * QS;          // [64][VS]
    float* Ps = Vs + 64 * VS;          // [128][QS]
    float* rE = Ps + 128 * QS;         // [64]
    float* cs = rE + 64;               // [64]

    const int b = blockIdx.x >> 4, h = blockIdx.x & 15;
    const int qt = (int)gridDim.y - 1 - (int)blockIdx.y;   // heavy blocks first
    const int q0 = qt * 128;
    const int tid = threadIdx.x;
    const int lane = tid & 31, wid = tid >> 5;
    const int gid = lane >> 2, ctg = lane & 3;
    const int wrow = wid * 16;

    const int nTA = 2 * qt + 2;           // phase-A k-tiles
    const int nB  = NTILE - nTA;

    if (tid < 64) {
        rE[tid] = rel_emb[tid * NHEAD + h];
        cs[tid] = g_vsuf[((size_t)b * (NTILE + 1) + nTA) * DIM + h * HDIM + tid];
    }

    // load Q tile [128][64]
    {
        const size_t baseQ = ((size_t)(b * SEQ + q0)) * D3 + h * HDIM;
        #pragma unroll
        for (int l = 0; l < 8; l++) {
            int e = tid + l * 256;
            int row = e >> 4, cq = (e & 15) << 2;
            float4 v = *(const float4*)(qkv + baseQ + (size_t)row * D3 + cq);
            *(float4*)(Qs + row * QS + cq) = v;
        }
    }

    float o[8][4];
    #pragma unroll
    for (int nt = 0; nt < 8; nt++)
        #pragma unroll
        for (int r = 0; r < 4; r++) o[nt][r] = 0.f;
    float dacc0 = 0.f, dacc1 = 0.f;

    const int qg0 = q0 + wrow + gid, qg1 = qg0 + 8;
    const int* relr0 = rel + ((size_t)b * SEQ + qg0) * SEQ;
    const int* relr1 = rel + ((size_t)b * SEQ + qg1) * SEQ;

    for (int kt = 0; kt < nTA; kt++) {
        const int k0 = kt * 64;
        __syncthreads();
        // load K,V tiles [64][64]
        const size_t baseK = ((size_t)(b * SEQ + k0)) * D3 + DIM + h * HDIM;
        #pragma unroll
        for (int l = 0; l < 4; l++) {
            int e = tid + l * 256;
            int row = e >> 4, cq = (e & 15) << 2;
            float4 kv = *(const float4*)(qkv + baseK + (size_t)row * D3 + cq);
            *(float4*)(Ks + row * QS + cq) = kv;
            float4 vv = *(const float4*)(qkv + baseK + DIM + (size_t)row * D3 + cq);
            *(float4*)(Vs + row * VS + cq) = vv;
        }
        __syncthreads();

        // S = Q K^T
        float s[8][4];
        #pragma unroll
        for (int nt = 0; nt < 8; nt++)
            #pragma unroll
            for (int r = 0; r < 4; r++) s[nt][r] = 0.f;
        #pragma unroll
        for (int ks = 0; ks < 8; ks++) {
            const int kb = ks << 3;
            uint32_t a[4];
            const float* ap = Qs + (wrow + gid) * QS + kb + ctg;
            a[0] = __float_as_uint(ap[0]);
            a[1] = __float_as_uint(ap[8 * QS]);
            a[2] = __float_as_uint(ap[4]);
            a[3] = __float_as_uint(ap[8 * QS + 4]);
            #pragma unroll
            for (int nt = 0; nt < 8; nt++) {
                uint32_t bb[2];
                const float* bp = Ks + (nt * 8 + gid) * QS + kb + ctg;
                bb[0] = __float_as_uint(bp[0]);
                bb[1] = __float_as_uint(bp[4]);
                mma_tf32(s[nt], a, bb);
            }
        }

        // p = exp(s * 0.125 * rel_emb[rel]) for k<=q else 1
        #pragma unroll
        for (int nt = 0; nt < 8; nt++) {
            const int kg = k0 + nt * 8 + 2 * ctg;
            int2 r0 = *(const int2*)(relr0 + kg);
            int2 r1 = *(const int2*)(relr1 + kg);
            float p00 = (kg     <= qg0) ? exp_small(s[nt][0] * 0.125f * rE[r0.x]) : 1.0f;
            float p01 = (kg + 1 <= qg0) ? exp_small(s[nt][1] * 0.125f * rE[r0.y]) : 1.0f;
            float p10 = (kg     <= qg1) ? exp_small(s[nt][2] * 0.125f * rE[r1.x]) : 1.0f;
            float p11 = (kg + 1 <= qg1) ? exp_small(s[nt][3] * 0.125f * rE[r1.y]) : 1.0f;
            dacc0 += p00 + p01;
            dacc1 += p10 + p11;
            float2 w0; w0.x = f2tff(p00); w0.y = f2tff(p01);
            float2 w1; w1.x = f2tff(p10); w1.y = f2tff(p11);
            *(float2*)(Ps + (wrow + gid) * QS + nt * 8 + 2 * ctg) = w0;
            *(float2*)(Ps + (wrow + 8 + gid) * QS + nt * 8 + 2 * ctg) = w1;
        }
        __syncwarp();

        // O += P V   (each warp reads only its own 16 Ps rows)
        #pragma unroll
        for (int ks = 0; ks < 8; ks++) {
            const int kb = ks << 3;
            uint32_t a[4];
            const float* ap = Ps + (wrow + gid) * QS + kb + ctg;
            a[0] = __float_as_uint(ap[0]);
            a[1] = __float_as_uint(ap[8 * QS]);
            a[2] = __float_as_uint(ap[4]);
            a[3] = __float_as_uint(ap[8 * QS + 4]);
            #pragma unroll
            for (int nt = 0; nt < 8; nt++) {
                uint32_t bb[2];
                const float* bp = Vs + (kb + ctg) * VS + nt * 8 + gid;
                bb[0] = __float_as_uint(bp[0]);
                bb[1] = __float_as_uint(bp[4 * VS]);
                mma_tf32(o[nt], a, bb);
            }
        }
    }

    // row denominators: reduce dacc over the 4 ctg lanes, add masked count
    dacc0 += __shfl_xor_sync(0xffffffffu, dacc0, 1);
    dacc0 += __shfl_xor_sync(0xffffffffu, dacc0, 2);
    dacc1 += __shfl_xor_sync(0xffffffffu, dacc1, 1);
    dacc1 += __shfl_xor_sync(0xffffffffu, dacc1, 2);
    const float i0 = 1.0f / (dacc0 + 64.0f * (float)nB);
    const float i1 = 1.0f / (dacc1 + 64.0f * (float)nB);

    float* o0 = out + ((size_t)b * SEQ + qg0) * DIM + h * HDIM;
    float* o1 = out + ((size_t)b * SEQ + qg1) * DIM + h * HDIM;
    #pragma unroll
    for (int nt = 0; nt < 8; nt++) {
        const int c = nt * 8 + 2 * ctg;
        const float cs0 = cs[c], cs1 = cs[c + 1];
        float2 w0, w1;
        w0.x = f2tff((o[nt][0] + cs0) * i0);
        w0.y = f2tff((o[nt][1] + cs1) * i0);
        w1.x = f2tff((o[nt][2] + cs0) * i1);
        w1.y = f2tff((o[nt][3] + cs1) * i1);
        *(float2*)(o0 + c) = w0;
        *(float2*)(o1 + c) = w1;
    }
}

// ---------------- launcher ----------------
extern "C" void kernel_launch(void* const* d_in, const int* in_sizes, int n_in,
                              void* d_out, int out_size)
{
    const float* x     = (const float*)d_in[0];
    const int*   rel   = (const int*)  d_in[1];
    const float* ln1w  = (const float*)d_in[2];
    const float* ln1b  = (const float*)d_in[3];
    const float* Wqkv  = (const float*)d_in[4];
    const float* bqkv  = (const float*)d_in[5];
    const float* Wo    = (const float*)d_in[6];
    const float* bo    = (const float*)d_in[7];
    const float* rele  = (const float*)d_in[8];
    const float* ln2w  = (const float*)d_in[9];
    const float* ln2b  = (const float*)d_in[10];
    const float* Wfc   = (const float*)d_in[11];
    const float* bfc   = (const float*)d_in[12];
    const float* Wp    = (const float*)d_in[13];
    const float* bp    = (const float*)d_in[14];
    float* out = (float*)d_out;

    float *h1, *qkv, *attn, *x1, *h2, *fc, *wq, *wo, *wf, *wp;
    cudaGetSymbolAddress((void**)&h1,   g_h1);
    cudaGetSymbolAddress((void**)&qkv,  g_qkv);
    cudaGetSymbolAddress((void**)&attn, g_attn);
    cudaGetSymbolAddress((void**)&x1,   g_x1);
    cudaGetSymbolAddress((void**)&h2,   g_h2);
    cudaGetSymbolAddress((void**)&fc,   g_fc);
    cudaGetSymbolAddress((void**)&wq,   g_wq);
    cudaGetSymbolAddress((void**)&wo,   g_wo);
    cudaGetSymbolAddress((void**)&wf,   g_wf);
    cudaGetSymbolAddress((void**)&wp,   g_wp);

    const int gemmSmem = (2 * ASZ + 2 * WSZ) * (int)sizeof(float);
    cudaFuncSetAttribute(gemm_tf32_kernel,
                         cudaFuncAttributeMaxDynamicSharedMemorySize, gemmSmem);
    const int attnSmem = (128*QS + 64*QS + 64*VS + 128*QS + 64 + 64)
                         * (int)sizeof(float);
    cudaFuncSetAttribute(attn_tc_kernel,
                         cudaFuncAttributeMaxDynamicSharedMemorySize, attnSmem);

    // 0. pre-round weights to tf32
    {
        int n;
        n = DIM*D3/4;  round_tf32_kernel<<<(n+255)/256, 256>>>((const float4*)Wqkv, (float4*)wq, n);
        n = DIM*DIM/4; round_tf32_kernel<<<(n+255)/256, 256>>>((const float4*)Wo,   (float4*)wo, n);
        n = DIM*D4/4;  round_tf32_kernel<<<(n+255)/256, 256>>>((const float4*)Wfc,  (float4*)wf, n);
        n = D4*DIM/4;  round_tf32_kernel<<<(n+255)/256, 256>>>((const float4*)Wp,   (float4*)wp, n);
    }

    // 1. LN1 (tf32-rounded out)
    ln_kernel<<<ROWS, 256>>>(x, ln1w, ln1b, h1);
    // 2. QKV GEMM (rounded out: feeds attention MMA)
    gemm_tf32_kernel<<<dim3(D3/128, ROWS/128), 256, gemmSmem>>>(h1, wq, bqkv, nullptr, qkv,
                                                                ROWS, D3, DIM, 0, 1);
    // 2b. V tile colsums + suffix scan (for fully-masked attention tiles)
    vtile_kernel<<<BATCH*NTILE, 256>>>(qkv);
    vsuf_kernel<<<BATCH, 1024>>>();
    // 3. Attention (tensor-core; rounded out: feeds Wo)
    attn_tc_kernel<<<dim3(BATCH*NHEAD, SEQ/128), 256, attnSmem>>>(qkv, rel, rele, attn);
    // 4. Wo + residual(x) -> x1 (fp32)
    gemm_tf32_kernel<<<dim3(DIM/128, ROWS/128), 256, gemmSmem>>>(attn, wo, bo, x, x1,
                                                                 ROWS, DIM, DIM, 0, 0);
    // 5. LN2 (rounded out)
    ln_kernel<<<ROWS, 256>>>(x1, ln2w, ln2b, h2);
    // 6. FC + GELU (rounded out: feeds Wp)
    gemm_tf32_kernel<<<dim3(D4/128, ROWS/128), 256, gemmSmem>>>(h2, wf, bfc, nullptr, fc,
                                                                ROWS, D4, DIM, 1, 1);
    // 7. Wp + residual(x1) -> out (fp32)
    gemm_tf32_kernel<<<dim3(DIM/128, ROWS/128), 256, gemmSmem>>>(fc, wp, bp, x1, out,
                                                                 ROWS, DIM, D4, 0, 0);
}

// round 12
// speedup vs baseline: 2.6793x; 1.7829x over previous
#include <cuda_runtime.h>
#include <cuda_pipeline.h>
#include <cuda_fp16.h>
#include <math.h>
#include <stdint.h>

// ---------------- problem constants ----------------
#define BATCH 2
#define SEQ   2048
#define DIM   1024
#define NHEAD 16
#define HDIM  64
#define ROWS  (BATCH*SEQ)          // 4096
#define D3    (3*DIM)              // 3072
#define D4    (4*DIM)              // 4096
#define NTILE 32                   // SEQ/64 k-tiles

// fp16 smem row strides (halves). 72 % 64 == 8  ->  word-stride 36 ≡ 4 (mod 32)
// -> fragment half2 loads at (row, 2*ctg) hit 32 distinct banks.
#define GST 72                     // GEMM tiles: [128][GST]
#define GTILE (128*GST)
#define QSH 72                     // attention Q: [128][QSH]
#define KSH 72                     // attention K: [64][KSH]
#define VSH 72                     // attention V: [64][VSH]
#define PSH 72                     // attention P: [128][PSH]

// ---------------- scratch (static device memory; 16B aligned) ---------------
__device__ __align__(16) __half g_h1  [(size_t)ROWS*DIM];
__device__ __align__(16) __half g_qkv [(size_t)ROWS*D3];
__device__ __align__(16) __half g_attn[(size_t)ROWS*DIM];
__device__ __align__(16) float  g_x1  [(size_t)ROWS*DIM];
__device__ __align__(16) __half g_h2  [(size_t)ROWS*DIM];
__device__ __align__(16) __half g_fc  [(size_t)ROWS*D4];
// fp16 transposed weights: Wt[N][K]
__device__ __align__(16) __half g_wq [(size_t)D3*DIM];
__device__ __align__(16) __half g_wo [(size_t)DIM*DIM];
__device__ __align__(16) __half g_wf [(size_t)D4*DIM];
__device__ __align__(16) __half g_wp [(size_t)DIM*D4];
// V per-tile colsums and suffix sums
__device__ __align__(16) float g_vtile[(size_t)BATCH*NTILE*DIM];
__device__ __align__(16) float g_vsuf [(size_t)BATCH*(NTILE+1)*DIM];

// ---------------- helpers ----------------
__device__ __forceinline__ uint32_t smem_u32(const void* p) {
    uint32_t a;
    asm("{ .reg .u64 t; cvta.to.shared.u64 t, %1; cvt.u32.u64 %0, t; }"
        : "=r"(a) : "l"(p));
    return a;
}

// fp16 mma: D[16,8] += A[16,16] * B[16,8], fp32 accumulate.
__device__ __forceinline__ void mma_f16(float* c, const uint32_t* a, const uint32_t* b) {
    asm volatile(
        "mma.sync.aligned.m16n8k16.row.col.f32.f16.f16.f32 "
        "{%0,%1,%2,%3}, {%4,%5,%6,%7}, {%8,%9}, {%0,%1,%2,%3};"
        : "+f"(c[0]), "+f"(c[1]), "+f"(c[2]), "+f"(c[3])
        : "r"(a[0]), "r"(a[1]), "r"(a[2]), "r"(a[3]), "r"(b[0]), "r"(b[1]));
}

// transposed 8x8 b16 matrix pair load (B operand of m16n8k16 from [k][n] smem)
__device__ __forceinline__ void ldsm_x2_trans(uint32_t* r, uint32_t addr) {
    asm volatile("ldmatrix.sync.aligned.m8n8.x2.trans.shared.b16 {%0,%1}, [%2];"
                 : "=r"(r[0]), "=r"(r[1]) : "r"(addr));
}

// exp via deg-7 Taylor (FMA pipe, no MUFU). |x| <~ 0.3 by construction.
__device__ __forceinline__ float exp_small(float x) {
    float p = fmaf(x, 1.f/5040.f, 1.f/720.f);
    p = fmaf(p, x, 1.f/120.f);
    p = fmaf(p, x, 1.f/24.f);
    p = fmaf(p, x, 1.f/6.f);
    p = fmaf(p, x, 0.5f);
    p = fmaf(p, x, 1.0f);
    p = fmaf(p, x, 1.0f);
    return p;
}

__device__ __forceinline__ float blockSum256(float v, float* s) {
    int lane = threadIdx.x & 31, w = threadIdx.x >> 5;
    #pragma unroll
    for (int o = 16; o; o >>= 1) v += __shfl_down_sync(0xffffffffu, v, o);
    if (!lane) s[w] = v;
    __syncthreads();
    if (threadIdx.x == 0) {
        float t = 0.f;
        #pragma unroll
        for (int i = 0; i < 8; i++) t += s[i];
        s[8] = t;
    }
    __syncthreads();
    float r = s[8];
    __syncthreads();
    return r;
}

// ---------------- weight transpose fp32[K,N] -> fp16[N,K] --------------------
__global__ void wtrans_kernel(const float* __restrict__ W, __half* __restrict__ Wt,
                              int K, int N)
{
    __shared__ float t[32][33];
    const int n0 = blockIdx.x * 32, k0 = blockIdx.y * 32;
    const int tx = threadIdx.x, ty = threadIdx.y;   // 32 x 8
    #pragma unroll
    for (int i = 0; i < 4; i++)
        t[ty + 8*i][tx] = W[(size_t)(k0 + ty + 8*i) * N + n0 + tx];
    __syncthreads();
    #pragma unroll
    for (int i = 0; i < 4; i++)
        Wt[(size_t)(n0 + ty + 8*i) * K + k0 + tx] = __float2half(t[tx][ty + 8*i]);
}

// ---------------- V per-tile column sums + suffix scan ----------------------
__global__ void vtile_kernel(const __half* __restrict__ qkv)
{
    const int b = blockIdx.x >> 5, kt = blockIdx.x & 31;
    const int k0 = kt * 64;
    float s[4] = {0.f, 0.f, 0.f, 0.f};
    const __half* vg = qkv + ((size_t)(b * SEQ + k0)) * D3 + 2 * DIM;
    for (int r = 0; r < 64; r++) {
        const __half* row = vg + (size_t)r * D3;
        #pragma unroll
        for (int l = 0; l < 4; l++) s[l] += __half2float(row[threadIdx.x + l * 256]);
    }
    float* o = g_vtile + ((size_t)(b * NTILE + kt)) * DIM;
    #pragma unroll
    for (int l = 0; l < 4; l++) o[threadIdx.x + l * 256] = s[l];
}

__global__ void vsuf_kernel()
{
    const int b = blockIdx.x;
    const int d = threadIdx.x;
    float acc = 0.f;
    g_vsuf[((size_t)b * (NTILE + 1) + NTILE) * DIM + d] = 0.f;
    for (int t = NTILE - 1; t >= 0; t--) {
        acc += g_vtile[((size_t)b * NTILE + t) * DIM + d];
        g_vsuf[((size_t)b * (NTILE + 1) + t) * DIM + d] = acc;
    }
}

// ---------------- LayerNorm (fp32 in, fp16 out) ----------
__global__ void ln_kernel(const float* __restrict__ x, const float* __restrict__ w,
                          const float* __restrict__ b, __half* __restrict__ y)
{
    __shared__ float red[9];
    const int row = blockIdx.x;
    const float* xr = x + (size_t)row * DIM;
    float v[4];
    #pragma unroll
    for (int l = 0; l < 4; l++) v[l] = xr[threadIdx.x + l * 256];
    float s = v[0] + v[1] + v[2] + v[3];
    const float mean = blockSum256(s, red) * (1.0f / DIM);
    float q = 0.f;
    #pragma unroll
    for (int l = 0; l < 4; l++) { float d = v[l] - mean; q += d * d; }
    const float ssq = blockSum256(q, red);
    const float stdv = sqrtf(ssq * (1.0f / (DIM - 1)));
    const float inv = 1.0f / (stdv + 1e-5f);
    __half* yr = y + (size_t)row * DIM;
    #pragma unroll
    for (int l = 0; l < 4; l++) {
        int c = threadIdx.x + l * 256;
        yr[c] = __float2half(w[c] * (v[l] - mean) * inv + b[c]);
    }
}

// ---------------- fp16 tensor-core GEMM --------------------------------------
// C[M,N] = A[M,K](half) @ Wt[N,K](half)^T + bias (+gelu)(+residual)
// BM=BN=128, BK=64, 256 threads = 8 warps; warp tile 64x32 (4x4 m16n8k16).
__global__ void __launch_bounds__(256, 2)
gemm_f16_kernel(const __half* __restrict__ A, const __half* __restrict__ Wt,
                const float* __restrict__ bias, const float* __restrict__ R,
                void* __restrict__ C, int M, int N, int K,
                int doGelu, int outHalf)
{
    extern __shared__ __half sh[];
    __half* smA = sh;                // [2][128][GST]
    __half* smB = sh + 2 * GTILE;    // [2][128][GST]

    const int tid  = threadIdx.x;
    const int lane = tid & 31, wid = tid >> 5;
    const int gid  = lane >> 2, ctg = lane & 3;
    const int wm0  = (wid >> 2) * 64;
    const int wn0  = (wid & 3) * 32;
    const int m0 = blockIdx.y << 7, n0 = blockIdx.x << 7;

    float acc[4][4][4];
    #pragma unroll
    for (int mt = 0; mt < 4; mt++)
        #pragma unroll
        for (int nt = 0; nt < 4; nt++)
            #pragma unroll
            for (int r = 0; r < 4; r++) acc[mt][nt][r] = 0.f;

    const int NC = K >> 6;

    auto loadChunk = [&](int ch, int buf) {
        const __half* Ag = A  + (size_t)m0 * K + ch * 64;
        const __half* Bg = Wt + (size_t)n0 * K + ch * 64;
        __half* Ad = smA + buf * GTILE;
        __half* Bd = smB + buf * GTILE;
        #pragma unroll
        for (int i = 0; i < 4; i++) {
            int g = tid + i * 256;               // 1024 16B-chunks per tile
            int row = g >> 3, c = g & 7;
            __pipeline_memcpy_async(Ad + row * GST + c * 8,
                                    Ag + (size_t)row * K + c * 8, 16);
            __pipeline_memcpy_async(Bd + row * GST + c * 8,
                                    Bg + (size_t)row * K + c * 8, 16);
        }
        __pipeline_commit();
    };

    loadChunk(0, 0);
    for (int it = 0; it < NC; it++) {
        if (it + 1 < NC) loadChunk(it + 1, (it + 1) & 1);
        else __pipeline_commit();
        __pipeline_wait_prior(1);
        __syncthreads();

        const __half* Ab = smA + (it & 1) * GTILE;
        const __half* Bb = smB + (it & 1) * GTILE;
        #pragma unroll
        for (int ks = 0; ks < 4; ks++) {
            const int kb = ks << 4;
            uint32_t af[4][4];
            #pragma unroll
            for (int mt = 0; mt < 4; mt++) {
                const __half* p = Ab + (wm0 + mt * 16 + gid) * GST + kb + 2 * ctg;
                af[mt][0] = *(const uint32_t*)(p);
                af[mt][1] = *(const uint32_t*)(p + 8 * GST);
                af[mt][2] = *(const uint32_t*)(p + 8);
                af[mt][3] = *(const uint32_t*)(p + 8 * GST + 8);
            }
            uint32_t bf[4][2];
            #pragma unroll
            for (int nt = 0; nt < 4; nt++) {
                const __half* p = Bb + (wn0 + nt * 8 + gid) * GST + kb + 2 * ctg;
                bf[nt][0] = *(const uint32_t*)(p);
                bf[nt][1] = *(const uint32_t*)(p + 8);
            }
            #pragma unroll
            for (int mt = 0; mt < 4; mt++)
                #pragma unroll
                for (int nt = 0; nt < 4; nt++)
                    mma_f16(acc[mt][nt], af[mt], bf[nt]);
        }
        __syncthreads();
    }

    // ---- epilogue (C fragment: rows gid/gid+8, cols 2ctg/2ctg+1) ----
    #pragma unroll
    for (int mt = 0; mt < 4; mt++) {
        #pragma unroll
        for (int half_ = 0; half_ < 2; half_++) {
            const int row = m0 + wm0 + mt * 16 + gid + half_ * 8;
            #pragma unroll
            for (int nt = 0; nt < 4; nt++) {
                const int col = n0 + wn0 + nt * 8 + 2 * ctg;
                float v0 = acc[mt][nt][half_ * 2 + 0] + bias[col];
                float v1 = acc[mt][nt][half_ * 2 + 1] + bias[col + 1];
                if (doGelu) {
                    float u = v0;
                    v0 = 0.5f * u * (1.0f + tanhf(0.7978845608028654f * (u + 0.044715f * u * u * u)));
                    u = v1;
                    v1 = 0.5f * u * (1.0f + tanhf(0.7978845608028654f * (u + 0.044715f * u * u * u)));
                }
                if (R) {
                    float2 rv = *(const float2*)(R + (size_t)row * N + col);
                    v0 += rv.x; v1 += rv.y;
                }
                if (outHalf) {
                    *(__half2*)((__half*)C + (size_t)row * N + col) =
                        __floats2half2_rn(v0, v1);
                } else {
                    float2 o; o.x = v0; o.y = v1;
                    *(float2*)((float*)C + (size_t)row * N + col) = o;
                }
            }
        }
    }
}

// ---------------- fp16 tensor-core attention ---------------------------------
// Q-tile 128 rows, K-tile 64 keys, 8 warps (warp w: rows 16w..16w+15).
// QK^T: fp16 mma from Qs[q][k], Ks[n][k]. PV: fp16 mma, P half in smem,
// V fragments via ldmatrix.x2.trans from Vs[k][d]. Masked tiles via g_vsuf.
__global__ void __launch_bounds__(256)
attn_f16_kernel(const __half* __restrict__ qkv, const int* __restrict__ rel,
                const float* __restrict__ rel_emb, __half* __restrict__ out)
{
    extern __shared__ __half smh[];
    __half* Qs = smh;                   // [128][QSH]
    __half* Ks = Qs + 128 * QSH;        // [64][KSH]
    __half* Vs = Ks + 64 * KSH;         // [64][VSH]
    __half* Ps = Vs + 64 * VSH;         // [128][PSH]
    float*  rE = (float*)(Ps + 128 * PSH);   // [64]
    float*  cs = rE + 64;                    // [64]

    const int b = blockIdx.x >> 4, h = blockIdx.x & 15;
    const int qt = (int)gridDim.y - 1 - (int)blockIdx.y;   // heavy blocks first
    const int q0 = qt * 128;
    const int tid = threadIdx.x;
    const int lane = tid & 31, wid = tid >> 5;
    const int gid = lane >> 2, ctg = lane & 3;
    const int wrow = wid * 16;
    const uint32_t vb = smem_u32(Vs);

    const int nTA = 2 * qt + 2;
    const int nB  = NTILE - nTA;

    if (tid < 64) {
        rE[tid] = rel_emb[tid * NHEAD + h];
        cs[tid] = g_vsuf[((size_t)b * (NTILE + 1) + nTA) * DIM + h * HDIM + tid];
    }

    // load Q tile [128][64] halves (8 chunks of 16B per row)
    {
        const __half* baseQ = qkv + ((size_t)(b * SEQ + q0)) * D3 + h * HDIM;
        #pragma unroll
        for (int l = 0; l < 4; l++) {
            int e = tid + l * 256;
            int row = e >> 3, c = e & 7;
            *(float4*)(Qs + row * QSH + c * 8) =
                *(const float4*)(baseQ + (size_t)row * D3 + c * 8);
        }
    }

    float o[8][4];
    #pragma unroll
    for (int nt = 0; nt < 8; nt++)
        #pragma unroll
        for (int r = 0; r < 4; r++) o[nt][r] = 0.f;
    float dacc0 = 0.f, dacc1 = 0.f;

    const int qg0 = q0 + wrow + gid, qg1 = qg0 + 8;
    const int* relr0 = rel + ((size_t)b * SEQ + qg0) * SEQ;
    const int* relr1 = rel + ((size_t)b * SEQ + qg1) * SEQ;

    for (int kt = 0; kt < nTA; kt++) {
        const int k0 = kt * 64;
        __syncthreads();
        // load K,V tiles [64][64] halves (4 chunks each per thread)
        const __half* baseK = qkv + ((size_t)(b * SEQ + k0)) * D3 + DIM + h * HDIM;
        #pragma unroll
        for (int l = 0; l < 2; l++) {
            int e = tid + l * 256;
            int row = e >> 3, c = e & 7;
            *(float4*)(Ks + row * KSH + c * 8) =
                *(const float4*)(baseK + (size_t)row * D3 + c * 8);
            *(float4*)(Vs + row * VSH + c * 8) =
                *(const float4*)(baseK + DIM + (size_t)row * D3 + c * 8);
        }
        __syncthreads();

        // S = Q K^T  (fp16, 4 k16 steps)
        float s[8][4];
        #pragma unroll
        for (int nt = 0; nt < 8; nt++)
            #pragma unroll
            for (int r = 0; r < 4; r++) s[nt][r] = 0.f;
        #pragma unroll
        for (int ks = 0; ks < 4; ks++) {
            const int kb = ks << 4;
            uint32_t a[4];
            const __half* ap = Qs + (wrow + gid) * QSH + kb + 2 * ctg;
            a[0] = *(const uint32_t*)(ap);
            a[1] = *(const uint32_t*)(ap + 8 * QSH);
            a[2] = *(const uint32_t*)(ap + 8);
            a[3] = *(const uint32_t*)(ap + 8 * QSH + 8);
            #pragma unroll
            for (int nt = 0; nt < 8; nt++) {
                uint32_t bb[2];
                const __half* bp = Ks + (nt * 8 + gid) * KSH + kb + 2 * ctg;
                bb[0] = *(const uint32_t*)(bp);
                bb[1] = *(const uint32_t*)(bp + 8);
                mma_f16(s[nt], a, bb);
            }
        }

        // p = exp(s * 0.125 * rel_emb[rel]) for k<=q else 1; store half
        #pragma unroll
        for (int nt = 0; nt < 8; nt++) {
            const int kg = k0 + nt * 8 + 2 * ctg;
            int2 r0 = *(const int2*)(relr0 + kg);
            int2 r1 = *(const int2*)(relr1 + kg);
            float p00 = (kg     <= qg0) ? exp_small(s[nt][0] * 0.125f * rE[r0.x]) : 1.0f;
            float p01 = (kg + 1 <= qg0) ? exp_small(s[nt][1] * 0.125f * rE[r0.y]) : 1.0f;
            float p10 = (kg     <= qg1) ? exp_small(s[nt][2] * 0.125f * rE[r1.x]) : 1.0f;
            float p11 = (kg + 1 <= qg1) ? exp_small(s[nt][3] * 0.125f * rE[r1.y]) : 1.0f;
            dacc0 += p00 + p01;
            dacc1 += p10 + p11;
            *(__half2*)(Ps + (wrow + gid) * PSH + nt * 8 + 2 * ctg) =
                __floats2half2_rn(p00, p01);
            *(__half2*)(Ps + (wrow + 8 + gid) * PSH + nt * 8 + 2 * ctg) =
                __floats2half2_rn(p10, p11);
        }
        __syncwarp();

        // O += P V  (fp16; B frags via ldmatrix.trans from Vs[k][d])
        #pragma unroll
        for (int ks = 0; ks < 4; ks++) {
            const int kb = ks << 4;
            uint32_t a[4];
            const __half* ap = Ps + (wrow + gid) * PSH + kb + 2 * ctg;
            a[0] = *(const uint32_t*)(ap);
            a[1] = *(const uint32_t*)(ap + 8 * PSH);
            a[2] = *(const uint32_t*)(ap + 8);
            a[3] = *(const uint32_t*)(ap + 8 * PSH + 8);
            const uint32_t vrow = vb + ((kb + (lane & 15)) * VSH) * 2;
            #pragma unroll
            for (int nt = 0; nt < 8; nt++) {
                uint32_t bb[2];
                ldsm_x2_trans(bb, vrow + nt * 16);
                mma_f16(o[nt], a, bb);
            }
        }
    }

    // row denominators: reduce dacc over the 4 ctg lanes, add masked count
    dacc0 += __shfl_xor_sync(0xffffffffu, dacc0, 1);
    dacc0 += __shfl_xor_sync(0xffffffffu, dacc0, 2);
    dacc1 += __shfl_xor_sync(0xffffffffu, dacc1, 1);
    dacc1 += __shfl_xor_sync(0xffffffffu, dacc1, 2);
    const float i0 = 1.0f / (dacc0 + 64.0f * (float)nB);
    const float i1 = 1.0f / (dacc1 + 64.0f * (float)nB);

    __half* o0 = out + ((size_t)b * SEQ + qg0) * DIM + h * HDIM;
    __half* o1 = out + ((size_t)b * SEQ + qg1) * DIM + h * HDIM;
    #pragma unroll
    for (int nt = 0; nt < 8; nt++) {
        const int c = nt * 8 + 2 * ctg;
        const float cs0 = cs[c], cs1 = cs[c + 1];
        *(__half2*)(o0 + c) = __floats2half2_rn((o[nt][0] + cs0) * i0,
                                                (o[nt][1] + cs1) * i0);
        *(__half2*)(o1 + c) = __floats2half2_rn((o[nt][2] + cs0) * i1,
                                                (o[nt][3] + cs1) * i1);
    }
}

// ---------------- launcher ----------------
extern "C" void kernel_launch(void* const* d_in, const int* in_sizes, int n_in,
                              void* d_out, int out_size)
{
    const float* x     = (const float*)d_in[0];
    const int*   rel   = (const int*)  d_in[1];
    const float* ln1w  = (const float*)d_in[2];
    const float* ln1b  = (const float*)d_in[3];
    const float* Wqkv  = (const float*)d_in[4];
    const float* bqkv  = (const float*)d_in[5];
    const float* Wo    = (const float*)d_in[6];
    const float* bo    = (const float*)d_in[7];
    const float* rele  = (const float*)d_in[8];
    const float* ln2w  = (const float*)d_in[9];
    const float* ln2b  = (const float*)d_in[10];
    const float* Wfc   = (const float*)d_in[11];
    const float* bfc   = (const float*)d_in[12];
    const float* Wp    = (const float*)d_in[13];
    const float* bp    = (const float*)d_in[14];
    float* out = (float*)d_out;

    __half *h1, *qkv, *attnh, *h2, *fc, *wq, *wo, *wf, *wp;
    float *x1;
    cudaGetSymbolAddress((void**)&h1,    g_h1);
    cudaGetSymbolAddress((void**)&qkv,   g_qkv);
    cudaGetSymbolAddress((void**)&attnh, g_attn);
    cudaGetSymbolAddress((void**)&x1,    g_x1);
    cudaGetSymbolAddress((void**)&h2,    g_h2);
    cudaGetSymbolAddress((void**)&fc,    g_fc);
    cudaGetSymbolAddress((void**)&wq,    g_wq);
    cudaGetSymbolAddress((void**)&wo,    g_wo);
    cudaGetSymbolAddress((void**)&wf,    g_wf);
    cudaGetSymbolAddress((void**)&wp,    g_wp);

    const int gemmSmem = 4 * GTILE * (int)sizeof(__half);   // 73728 B
    cudaFuncSetAttribute(gemm_f16_kernel,
                         cudaFuncAttributeMaxDynamicSharedMemorySize, gemmSmem);
    const int attnSmem = (128*QSH + 64*KSH + 64*VSH + 128*PSH) * (int)sizeof(__half)
                         + 128 * (int)sizeof(float);
    cudaFuncSetAttribute(attn_f16_kernel,
                         cudaFuncAttributeMaxDynamicSharedMemorySize, attnSmem);

    // 0. transpose + fp16-convert weights: Wt[N][K]
    {
        dim3 blk(32, 8);
        wtrans_kernel<<<dim3(D3/32,  DIM/32), blk>>>(Wqkv, wq, DIM, D3);
        wtrans_kernel<<<dim3(DIM/32, DIM/32), blk>>>(Wo,   wo, DIM, DIM);
        wtrans_kernel<<<dim3(D4/32,  DIM/32), blk>>>(Wfc,  wf, DIM, D4);
        wtrans_kernel<<<dim3(DIM/32, D4/32),  blk>>>(Wp,   wp, D4,  DIM);
    }

    // 1. LN1 -> h1 (fp16)
    ln_kernel<<<ROWS, 256>>>(x, ln1w, ln1b, h1);
    // 2. QKV GEMM -> qkv (fp16)
    gemm_f16_kernel<<<dim3(D3/128, ROWS/128), 256, gemmSmem>>>(
        h1, wq, bqkv, nullptr, qkv, ROWS, D3, DIM, 0, 1);
    // 2b. V colsums + suffix scan
    vtile_kernel<<<BATCH*NTILE, 256>>>(qkv);
    vsuf_kernel<<<BATCH, 1024>>>();
    // 3. Attention -> attnh (fp16)
    attn_f16_kernel<<<dim3(BATCH*NHEAD, SEQ/128), 256, attnSmem>>>(qkv, rel, rele, attnh);
    // 4. Wo + residual(x) -> x1 (fp32)
    gemm_f16_kernel<<<dim3(DIM/128, ROWS/128), 256, gemmSmem>>>(
        attnh, wo, bo, x, x1, ROWS, DIM, DIM, 0, 0);
    // 5. LN2 -> h2 (fp16)
    ln_kernel<<<ROWS, 256>>>(x1, ln2w, ln2b, h2);
    // 6. FC + GELU -> fc (fp16)
    gemm_f16_kernel<<<dim3(D4/128, ROWS/128), 256, gemmSmem>>>(
        h2, wf, bfc, nullptr, fc, ROWS, D4, DIM, 1, 1);
    // 7. Wp + residual(x1) -> out (fp32)
    gemm_f16_kernel<<<dim3(DIM/128, ROWS/128), 256, gemmSmem>>>(
        fc, wp, bp, x1, out, ROWS, DIM, D4, 0, 0);
}

// round 16
// speedup vs baseline: 2.7525x; 1.0273x over previous
#include <cuda_runtime.h>
#include <cuda_pipeline.h>
#include <cuda_fp16.h>
#include <math.h>
#include <stdint.h>

// ---------------- problem constants ----------------
#define BATCH 2
#define SEQ   2048
#define DIM   1024
#define NHEAD 16
#define HDIM  64
#define ROWS  (BATCH*SEQ)          // 4096
#define D3    (3*DIM)              // 3072
#define D4    (4*DIM)              // 4096
#define NTILE 32                   // SEQ/64 k-tiles

// fp16 smem row strides (halves). 72 % 64 == 8 -> word-stride 36 ≡ 4 (mod 32)
// -> fragment half2 loads at (row, 2*ctg) hit 32 distinct banks.
#define GST 72                     // GEMM tiles: [128][GST]
#define GTILE (128*GST)
#define QSH 72                     // attention Q: [128][QSH]
#define KSH 72                     // attention K: [64][KSH]
#define VSH 72                     // attention V: [64][VSH]

// ---------------- scratch (static device memory; 16B aligned) ---------------
__device__ __align__(16) __half g_h1  [(size_t)ROWS*DIM];
__device__ __align__(16) __half g_qkv [(size_t)ROWS*D3];
__device__ __align__(16) __half g_attn[(size_t)ROWS*DIM];
__device__ __align__(16) float  g_x1  [(size_t)ROWS*DIM];
__device__ __align__(16) __half g_h2  [(size_t)ROWS*DIM];
__device__ __align__(16) __half g_fc  [(size_t)ROWS*D4];
// fp16 transposed weights: Wt[N][K]
__device__ __align__(16) __half g_wq [(size_t)D3*DIM];
__device__ __align__(16) __half g_wo [(size_t)DIM*DIM];
__device__ __align__(16) __half g_wf [(size_t)D4*DIM];
__device__ __align__(16) __half g_wp [(size_t)DIM*D4];
// V per-tile colsums and suffix sums
__device__ __align__(16) float g_vtile[(size_t)BATCH*NTILE*DIM];
__device__ __align__(16) float g_vsuf [(size_t)BATCH*(NTILE+1)*DIM];

// ---------------- helpers ----------------
__device__ __forceinline__ uint32_t smem_u32(const void* p) {
    uint32_t a;
    asm("{ .reg .u64 t; cvta.to.shared.u64 t, %1; cvt.u32.u64 %0, t; }"
        : "=r"(a) : "l"(p));
    return a;
}

// fp16 mma: D[16,8] += A[16,16] * B[16,8], fp32 accumulate.
__device__ __forceinline__ void mma_f16(float* c, const uint32_t* a, const uint32_t* b) {
    asm volatile(
        "mma.sync.aligned.m16n8k16.row.col.f32.f16.f16.f32 "
        "{%0,%1,%2,%3}, {%4,%5,%6,%7}, {%8,%9}, {%0,%1,%2,%3};"
        : "+f"(c[0]), "+f"(c[1]), "+f"(c[2]), "+f"(c[3])
        : "r"(a[0]), "r"(a[1]), "r"(a[2]), "r"(a[3]), "r"(b[0]), "r"(b[1]));
}

// transposed 8x8 b16 matrix pair load (B operand of m16n8k16 from [k][n] smem)
__device__ __forceinline__ void ldsm_x2_trans(uint32_t* r, uint32_t addr) {
    asm volatile("ldmatrix.sync.aligned.m8n8.x2.trans.shared.b16 {%0,%1}, [%2];"
                 : "=r"(r[0]), "=r"(r[1]) : "r"(addr));
}

__device__ __forceinline__ uint32_t packh2(float a, float b) {
    __half2 h = __floats2half2_rn(a, b);
    return *(uint32_t*)&h;
}

// exp via deg-5 Taylor (FMA pipe). |x| <~ 0.3 by construction -> err ~1e-6.
__device__ __forceinline__ float exp_small(float x) {
    float p = fmaf(x, 1.f/120.f, 1.f/24.f);
    p = fmaf(p, x, 1.f/6.f);
    p = fmaf(p, x, 0.5f);
    p = fmaf(p, x, 1.0f);
    p = fmaf(p, x, 1.0f);
    return p;
}

__device__ __forceinline__ float blockSum256(float v, float* s) {
    int lane = threadIdx.x & 31, w = threadIdx.x >> 5;
    #pragma unroll
    for (int o = 16; o; o >>= 1) v += __shfl_down_sync(0xffffffffu, v, o);
    if (!lane) s[w] = v;
    __syncthreads();
    if (threadIdx.x == 0) {
        float t = 0.f;
        #pragma unroll
        for (int i = 0; i < 8; i++) t += s[i];
        s[8] = t;
    }
    __syncthreads();
    float r = s[8];
    __syncthreads();
    return r;
}

// ---------------- weight transpose fp32[K,N] -> fp16[N,K] --------------------
__global__ void wtrans_kernel(const float* __restrict__ W, __half* __restrict__ Wt,
                              int K, int N)
{
    __shared__ float t[32][33];
    const int n0 = blockIdx.x * 32, k0 = blockIdx.y * 32;
    const int tx = threadIdx.x, ty = threadIdx.y;   // 32 x 8
    #pragma unroll
    for (int i = 0; i < 4; i++)
        t[ty + 8*i][tx] = W[(size_t)(k0 + ty + 8*i) * N + n0 + tx];
    __syncthreads();
    #pragma unroll
    for (int i = 0; i < 4; i++)
        Wt[(size_t)(n0 + ty + 8*i) * K + k0 + tx] = __float2half(t[tx][ty + 8*i]);
}

// ---------------- V per-tile column sums + suffix scan ----------------------
__global__ void vtile_kernel(const __half* __restrict__ qkv)
{
    const int b = blockIdx.x >> 5, kt = blockIdx.x & 31;
    const int k0 = kt * 64;
    float s[4] = {0.f, 0.f, 0.f, 0.f};
    const __half* vg = qkv + ((size_t)(b * SEQ + k0)) * D3 + 2 * DIM;
    for (int r = 0; r < 64; r++) {
        const __half* row = vg + (size_t)r * D3;
        #pragma unroll
        for (int l = 0; l < 4; l++) s[l] += __half2float(row[threadIdx.x + l * 256]);
    }
    float* o = g_vtile + ((size_t)(b * NTILE + kt)) * DIM;
    #pragma unroll
    for (int l = 0; l < 4; l++) o[threadIdx.x + l * 256] = s[l];
}

__global__ void vsuf_kernel()
{
    const int b = blockIdx.x;
    const int d = threadIdx.x;
    float acc = 0.f;
    g_vsuf[((size_t)b * (NTILE + 1) + NTILE) * DIM + d] = 0.f;
    for (int t = NTILE - 1; t >= 0; t--) {
        acc += g_vtile[((size_t)b * NTILE + t) * DIM + d];
        g_vsuf[((size_t)b * (NTILE + 1) + t) * DIM + d] = acc;
    }
}

// ---------------- LayerNorm (fp32 in, fp16 out) ----------
__global__ void ln_kernel(const float* __restrict__ x, const float* __restrict__ w,
                          const float* __restrict__ b, __half* __restrict__ y)
{
    __shared__ float red[9];
    const int row = blockIdx.x;
    const float* xr = x + (size_t)row * DIM;
    float v[4];
    #pragma unroll
    for (int l = 0; l < 4; l++) v[l] = xr[threadIdx.x + l * 256];
    float s = v[0] + v[1] + v[2] + v[3];
    const float mean = blockSum256(s, red) * (1.0f / DIM);
    float q = 0.f;
    #pragma unroll
    for (int l = 0; l < 4; l++) { float d = v[l] - mean; q += d * d; }
    const float ssq = blockSum256(q, red);
    const float stdv = sqrtf(ssq * (1.0f / (DIM - 1)));
    const float inv = 1.0f / (stdv + 1e-5f);
    __half* yr = y + (size_t)row * DIM;
    #pragma unroll
    for (int l = 0; l < 4; l++) {
        int c = threadIdx.x + l * 256;
        yr[c] = __float2half(w[c] * (v[l] - mean) * inv + b[c]);
    }
}

// ---------------- fp16 tensor-core GEMM (R12-proven structure) ---------------
// C[M,N] = A[M,K](half) @ Wt[N,K](half)^T + bias (+gelu)(+residual)
// BM=BN=128, BK=64, 256 threads = 8 warps; warp tile 64x32 (4x4 m16n8k16).
__global__ void __launch_bounds__(256, 2)
gemm_f16_kernel(const __half* __restrict__ A, const __half* __restrict__ Wt,
                const float* __restrict__ bias, const float* __restrict__ R,
                void* __restrict__ C, int M, int N, int K,
                int doGelu, int outHalf)
{
    extern __shared__ __half sh[];
    __half* smA = sh;                // [2][128][GST]
    __half* smB = sh + 2 * GTILE;    // [2][128][GST]

    const int tid  = threadIdx.x;
    const int lane = tid & 31, wid = tid >> 5;
    const int gid  = lane >> 2, ctg = lane & 3;
    const int wm0  = (wid >> 2) * 64;
    const int wn0  = (wid & 3) * 32;
    const int m0 = blockIdx.y << 7, n0 = blockIdx.x << 7;

    float acc[4][4][4];
    #pragma unroll
    for (int mt = 0; mt < 4; mt++)
        #pragma unroll
        for (int nt = 0; nt < 4; nt++)
            #pragma unroll
            for (int r = 0; r < 4; r++) acc[mt][nt][r] = 0.f;

    const int NC = K >> 6;

    auto loadChunk = [&](int ch, int buf) {
        const __half* Ag = A  + (size_t)m0 * K + ch * 64;
        const __half* Bg = Wt + (size_t)n0 * K + ch * 64;
        __half* Ad = smA + buf * GTILE;
        __half* Bd = smB + buf * GTILE;
        #pragma unroll
        for (int i = 0; i < 4; i++) {
            int g = tid + i * 256;               // 1024 16B-chunks per tile
            int row = g >> 3, c = g & 7;
            __pipeline_memcpy_async(Ad + row * GST + c * 8,
                                    Ag + (size_t)row * K + c * 8, 16);
            __pipeline_memcpy_async(Bd + row * GST + c * 8,
                                    Bg + (size_t)row * K + c * 8, 16);
        }
        __pipeline_commit();
    };

    loadChunk(0, 0);
    for (int it = 0; it < NC; it++) {
        if (it + 1 < NC) loadChunk(it + 1, (it + 1) & 1);
        else __pipeline_commit();
        __pipeline_wait_prior(1);
        __syncthreads();

        const __half* Ab = smA + (it & 1) * GTILE;
        const __half* Bb = smB + (it & 1) * GTILE;
        #pragma unroll
        for (int ks = 0; ks < 4; ks++) {
            const int kb = ks << 4;
            uint32_t af[4][4];
            #pragma unroll
            for (int mt = 0; mt < 4; mt++) {
                const __half* p = Ab + (wm0 + mt * 16 + gid) * GST + kb + 2 * ctg;
                af[mt][0] = *(const uint32_t*)(p);
                af[mt][1] = *(const uint32_t*)(p + 8 * GST);
                af[mt][2] = *(const uint32_t*)(p + 8);
                af[mt][3] = *(const uint32_t*)(p + 8 * GST + 8);
            }
            uint32_t bf[4][2];
            #pragma unroll
            for (int nt = 0; nt < 4; nt++) {
                const __half* p = Bb + (wn0 + nt * 8 + gid) * GST + kb + 2 * ctg;
                bf[nt][0] = *(const uint32_t*)(p);
                bf[nt][1] = *(const uint32_t*)(p + 8);
            }
            #pragma unroll
            for (int mt = 0; mt < 4; mt++)
                #pragma unroll
                for (int nt = 0; nt < 4; nt++)
                    mma_f16(acc[mt][nt], af[mt], bf[nt]);
        }
        __syncthreads();
    }

    // ---- epilogue (C fragment: rows gid/gid+8, cols 2ctg/2ctg+1) ----
    #pragma unroll
    for (int mt = 0; mt < 4; mt++) {
        #pragma unroll
        for (int half_ = 0; half_ < 2; half_++) {
            const int row = m0 + wm0 + mt * 16 + gid + half_ * 8;
            #pragma unroll
            for (int nt = 0; nt < 4; nt++) {
                const int col = n0 + wn0 + nt * 8 + 2 * ctg;
                float v0 = acc[mt][nt][half_ * 2 + 0] + bias[col];
                float v1 = acc[mt][nt][half_ * 2 + 1] + bias[col + 1];
                if (doGelu) {
                    float u = v0;
                    v0 = 0.5f * u * (1.0f + tanhf(0.7978845608028654f * (u + 0.044715f * u * u * u)));
                    u = v1;
                    v1 = 0.5f * u * (1.0f + tanhf(0.7978845608028654f * (u + 0.044715f * u * u * u)));
                }
                if (R) {
                    float2 rv = *(const float2*)(R + (size_t)row * N + col);
                    v0 += rv.x; v1 += rv.y;
                }
                if (outHalf) {
                    *(__half2*)((__half*)C + (size_t)row * N + col) =
                        __floats2half2_rn(v0, v1);
                } else {
                    float2 o; o.x = v0; o.y = v1;
                    *(float2*)((float*)C + (size_t)row * N + col) = o;
                }
            }
        }
    }
}

// ---------------- fp16 tensor-core attention (register-resident P) -----------
// Q-tile 128 rows, K-tile 64 keys, 8 warps (warp w: rows 16w..16w+15).
// QK^T: scalar frag loads (R12-proven). P stays in registers (S-frag layout ==
// A-frag layout). PV: V frags via ldmatrix.x2.trans. Masked tiles via g_vsuf.
__global__ void __launch_bounds__(256)
attn_f16_kernel(const __half* __restrict__ qkv, const int* __restrict__ rel,
                const float* __restrict__ rel_emb, __half* __restrict__ out)
{
    extern __shared__ __half smh[];
    __half* Qs = smh;                   // [128][QSH]
    __half* Ks = Qs + 128 * QSH;        // [64][KSH]
    __half* Vs = Ks + 64 * KSH;         // [64][VSH]
    float*  rE = (float*)(Vs + 64 * VSH);    // [64]
    float*  cs = rE + 64;                    // [64]

    const int b = blockIdx.x >> 4, h = blockIdx.x & 15;
    const int qt = (int)gridDim.y - 1 - (int)blockIdx.y;   // heavy blocks first
    const int q0 = qt * 128;
    const int tid = threadIdx.x;
    const int lane = tid & 31, wid = tid >> 5;
    const int gid = lane >> 2, ctg = lane & 3;
    const int wrow = wid * 16;
    const uint32_t vb = smem_u32(Vs);

    const int nTA = 2 * qt + 2;
    const int nB  = NTILE - nTA;

    if (tid < 64) {
        rE[tid] = rel_emb[tid * NHEAD + h];
        cs[tid] = g_vsuf[((size_t)b * (NTILE + 1) + nTA) * DIM + h * HDIM + tid];
    }

    // load Q tile [128][64] halves
    {
        const __half* baseQ = qkv + ((size_t)(b * SEQ + q0)) * D3 + h * HDIM;
        #pragma unroll
        for (int l = 0; l < 4; l++) {
            int e = tid + l * 256;
            int row = e >> 3, c = e & 7;
            *(float4*)(Qs + row * QSH + c * 8) =
                *(const float4*)(baseQ + (size_t)row * D3 + c * 8);
        }
    }

    float o[8][4];
    #pragma unroll
    for (int nt = 0; nt < 8; nt++)
        #pragma unroll
        for (int r = 0; r < 4; r++) o[nt][r] = 0.f;
    float dacc0 = 0.f, dacc1 = 0.f;

    const int qg0 = q0 + wrow + gid, qg1 = qg0 + 8;
    const int* relr0 = rel + ((size_t)b * SEQ + qg0) * SEQ;
    const int* relr1 = rel + ((size_t)b * SEQ + qg1) * SEQ;

    for (int kt = 0; kt < nTA; kt++) {
        const int k0 = kt * 64;
        __syncthreads();
        // load K,V tiles [64][64]
        const __half* baseK = qkv + ((size_t)(b * SEQ + k0)) * D3 + DIM + h * HDIM;
        #pragma unroll
        for (int l = 0; l < 2; l++) {
            int e = tid + l * 256;
            int row = e >> 3, c = e & 7;
            *(float4*)(Ks + row * KSH + c * 8) =
                *(const float4*)(baseK + (size_t)row * D3 + c * 8);
            *(float4*)(Vs + row * VSH + c * 8) =
                *(const float4*)(baseK + DIM + (size_t)row * D3 + c * 8);
        }
        __syncthreads();

        // S = Q K^T  (fp16, 4 k16 steps; scalar frag loads as in R12)
        float s[8][4];
        #pragma unroll
        for (int nt = 0; nt < 8; nt++)
            #pragma unroll
            for (int r = 0; r < 4; r++) s[nt][r] = 0.f;
        #pragma unroll
        for (int ks = 0; ks < 4; ks++) {
            const int kb = ks << 4;
            uint32_t a[4];
            const __half* ap = Qs + (wrow + gid) * QSH + kb + 2 * ctg;
            a[0] = *(const uint32_t*)(ap);
            a[1] = *(const uint32_t*)(ap + 8 * QSH);
            a[2] = *(const uint32_t*)(ap + 8);
            a[3] = *(const uint32_t*)(ap + 8 * QSH + 8);
            #pragma unroll
            for (int nt = 0; nt < 8; nt++) {
                uint32_t bb[2];
                const __half* bp = Ks + (nt * 8 + gid) * KSH + kb + 2 * ctg;
                bb[0] = *(const uint32_t*)(bp);
                bb[1] = *(const uint32_t*)(bp + 8);
                mma_f16(s[nt], a, bb);
            }
        }

        // p = exp(s * 0.125 * rel_emb[rel]) for k<=q else 1 (in registers)
        #pragma unroll
        for (int nt = 0; nt < 8; nt++) {
            const int kg = k0 + nt * 8 + 2 * ctg;
            int2 r0 = *(const int2*)(relr0 + kg);
            int2 r1 = *(const int2*)(relr1 + kg);
            float p00 = (kg     <= qg0) ? exp_small(s[nt][0] * 0.125f * rE[r0.x]) : 1.0f;
            float p01 = (kg + 1 <= qg0) ? exp_small(s[nt][1] * 0.125f * rE[r0.y]) : 1.0f;
            float p10 = (kg     <= qg1) ? exp_small(s[nt][2] * 0.125f * rE[r1.x]) : 1.0f;
            float p11 = (kg + 1 <= qg1) ? exp_small(s[nt][3] * 0.125f * rE[r1.y]) : 1.0f;
            dacc0 += p00 + p01;
            dacc1 += p10 + p11;
            s[nt][0] = p00; s[nt][1] = p01; s[nt][2] = p10; s[nt][3] = p11;
        }

        // O += P V ; A-frags packed straight from registers
        // (a0=P[gid][kb+2ctg..], a1=P[gid+8][..], a2=P[gid][kb+8+..], a3=P[gid+8][kb+8..])
        #pragma unroll
        for (int ks = 0; ks < 4; ks++) {
            const int kb = ks << 4;
            uint32_t a[4];
            a[0] = packh2(s[2*ks][0],   s[2*ks][1]);
            a[1] = packh2(s[2*ks][2],   s[2*ks][3]);
            a[2] = packh2(s[2*ks+1][0], s[2*ks+1][1]);
            a[3] = packh2(s[2*ks+1][2], s[2*ks+1][3]);
            const uint32_t vrow = vb + (uint32_t)(((kb + (lane & 15)) * VSH) * 2);
            #pragma unroll
            for (int nt = 0; nt < 8; nt++) {
                uint32_t bb[2];
                ldsm_x2_trans(bb, vrow + nt * 16);
                mma_f16(o[nt], a, bb);
            }
        }
    }

    // row denominators: reduce dacc over the 4 ctg lanes, add masked count
    dacc0 += __shfl_xor_sync(0xffffffffu, dacc0, 1);
    dacc0 += __shfl_xor_sync(0xffffffffu, dacc0, 2);
    dacc1 += __shfl_xor_sync(0xffffffffu, dacc1, 1);
    dacc1 += __shfl_xor_sync(0xffffffffu, dacc1, 2);
    const float i0 = 1.0f / (dacc0 + 64.0f * (float)nB);
    const float i1 = 1.0f / (dacc1 + 64.0f * (float)nB);

    __half* o0 = out + ((size_t)b * SEQ + qg0) * DIM + h * HDIM;
    __half* o1 = out + ((size_t)b * SEQ + qg1) * DIM + h * HDIM;
    #pragma unroll
    for (int nt = 0; nt < 8; nt++) {
        const int c = nt * 8 + 2 * ctg;
        const float cs0 = cs[c], cs1 = cs[c + 1];
        *(__half2*)(o0 + c) = __floats2half2_rn((o[nt][0] + cs0) * i0,
                                                (o[nt][1] + cs1) * i0);
        *(__half2*)(o1 + c) = __floats2half2_rn((o[nt][2] + cs0) * i1,
                                                (o[nt][3] + cs1) * i1);
    }
}

// ---------------- launcher ----------------
extern "C" void kernel_launch(void* const* d_in, const int* in_sizes, int n_in,
                              void* d_out, int out_size)
{
    const float* x     = (const float*)d_in[0];
    const int*   rel   = (const int*)  d_in[1];
    const float* ln1w  = (const float*)d_in[2];
    const float* ln1b  = (const float*)d_in[3];
    const float* Wqkv  = (const float*)d_in[4];
    const float* bqkv  = (const float*)d_in[5];
    const float* Wo    = (const float*)d_in[6];
    const float* bo    = (const float*)d_in[7];
    const float* rele  = (const float*)d_in[8];
    const float* ln2w  = (const float*)d_in[9];
    const float* ln2b  = (const float*)d_in[10];
    const float* Wfc   = (const float*)d_in[11];
    const float* bfc   = (const float*)d_in[12];
    const float* Wp    = (const float*)d_in[13];
    const float* bp    = (const float*)d_in[14];
    float* out = (float*)d_out;

    __half *h1, *qkv, *attnh, *h2, *fc, *wq, *wo, *wf, *wp;
    float *x1;
    cudaGetSymbolAddress((void**)&h1,    g_h1);
    cudaGetSymbolAddress((void**)&qkv,   g_qkv);
    cudaGetSymbolAddress((void**)&attnh, g_attn);
    cudaGetSymbolAddress((void**)&x1,    g_x1);
    cudaGetSymbolAddress((void**)&h2,    g_h2);
    cudaGetSymbolAddress((void**)&fc,    g_fc);
    cudaGetSymbolAddress((void**)&wq,    g_wq);
    cudaGetSymbolAddress((void**)&wo,    g_wo);
    cudaGetSymbolAddress((void**)&wf,    g_wf);
    cudaGetSymbolAddress((void**)&wp,    g_wp);

    const int gemmSmem = 4 * GTILE * (int)sizeof(__half);   // 73728 B
    cudaFuncSetAttribute(gemm_f16_kernel,
                         cudaFuncAttributeMaxDynamicSharedMemorySize, gemmSmem);
    const int attnSmem = (128*QSH + 64*KSH + 64*VSH) * (int)sizeof(__half)
                         + 128 * (int)sizeof(float);        // 37376 B
    cudaFuncSetAttribute(attn_f16_kernel,
                         cudaFuncAttributeMaxDynamicSharedMemorySize, attnSmem);

    // 0. transpose + fp16-convert weights: Wt[N][K]
    {
        dim3 blk(32, 8);
        wtrans_kernel<<<dim3(D3/32,  DIM/32), blk>>>(Wqkv, wq, DIM, D3);
        wtrans_kernel<<<dim3(DIM/32, DIM/32), blk>>>(Wo,   wo, DIM, DIM);
        wtrans_kernel<<<dim3(D4/32,  DIM/32), blk>>>(Wfc,  wf, DIM, D4);
        wtrans_kernel<<<dim3(DIM/32, D4/32),  blk>>>(Wp,   wp, D4,  DIM);
    }

    // 1. LN1 -> h1 (fp16)
    ln_kernel<<<ROWS, 256>>>(x, ln1w, ln1b, h1);
    // 2. QKV GEMM -> qkv (fp16)
    gemm_f16_kernel<<<dim3(D3/128, ROWS/128), 256, gemmSmem>>>(
        h1, wq, bqkv, nullptr, qkv, ROWS, D3, DIM, 0, 1);
    // 2b. V colsums + suffix scan
    vtile_kernel<<<BATCH*NTILE, 256>>>(qkv);
    vsuf_kernel<<<BATCH, 1024>>>();
    // 3. Attention -> attnh (fp16)
    attn_f16_kernel<<<dim3(BATCH*NHEAD, SEQ/128), 256, attnSmem>>>(qkv, rel, rele, attnh);
    // 4. Wo + residual(x) -> x1 (fp32)
    gemm_f16_kernel<<<dim3(DIM/128, ROWS/128), 256, gemmSmem>>>(
        attnh, wo, bo, x, x1, ROWS, DIM, DIM, 0, 0);
    // 5. LN2 -> h2 (fp16)
    ln_kernel<<<ROWS, 256>>>(x1, ln2w, ln2b, h2);
    // 6. FC + GELU -> fc (fp16)
    gemm_f16_kernel<<<dim3(D4/128, ROWS/128), 256, gemmSmem>>>(
        h2, wf, bfc, nullptr, fc, ROWS, D4, DIM, 1, 1);
    // 7. Wp + residual(x1) -> out (fp32)
    gemm_f16_kernel<<<dim3(DIM/128, ROWS/128), 256, gemmSmem>>>(
        fc, wp, bp, x1, out, ROWS, DIM, D4, 0, 0);
}

// round 17
// speedup vs baseline: 2.7742x; 1.0079x over previous
#include <cuda_runtime.h>
#include <cuda_pipeline.h>
#include <cuda_fp16.h>
#include <math.h>
#include <stdint.h>

// ---------------- problem constants ----------------
#define BATCH 2
#define SEQ   2048
#define DIM   1024
#define NHEAD 16
#define HDIM  64
#define ROWS  (BATCH*SEQ)          // 4096
#define D3    (3*DIM)              // 3072
#define D4    (4*DIM)              // 4096
#define NTILE 32                   // SEQ/64 k-tiles

// fp16 smem row strides (halves). 72 % 64 == 8 -> word-stride 36 ≡ 4 (mod 32)
// -> fragment half2 loads at (row, 2*ctg) hit 32 distinct banks.
#define GST 72                     // GEMM tiles: [128][GST]
#define GTILE (128*GST)
#define QSH 72                     // attention Q: [128][QSH]
#define KSH 72                     // attention K: [2][64][KSH]
#define VSH 72                     // attention V: [2][64][VSH]

// ---------------- scratch (static device memory; 16B aligned) ---------------
__device__ __align__(16) __half g_h1  [(size_t)ROWS*DIM];
__device__ __align__(16) __half g_qkv [(size_t)ROWS*D3];
__device__ __align__(16) __half g_attn[(size_t)ROWS*DIM];
__device__ __align__(16) float  g_x1  [(size_t)ROWS*DIM];
__device__ __align__(16) __half g_h2  [(size_t)ROWS*DIM];
__device__ __align__(16) __half g_fc  [(size_t)ROWS*D4];
// fp16 transposed weights: Wt[N][K]
__device__ __align__(16) __half g_wq [(size_t)D3*DIM];
__device__ __align__(16) __half g_wo [(size_t)DIM*DIM];
__device__ __align__(16) __half g_wf [(size_t)D4*DIM];
__device__ __align__(16) __half g_wp [(size_t)DIM*D4];
// V per-tile colsums and suffix sums
__device__ __align__(16) float g_vtile[(size_t)BATCH*NTILE*DIM];
__device__ __align__(16) float g_vsuf [(size_t)BATCH*(NTILE+1)*DIM];

// ---------------- helpers ----------------
__device__ __forceinline__ uint32_t smem_u32(const void* p) {
    uint32_t a;
    asm("{ .reg .u64 t; cvta.to.shared.u64 t, %1; cvt.u32.u64 %0, t; }"
        : "=r"(a) : "l"(p));
    return a;
}

// fp16 mma: D[16,8] += A[16,16] * B[16,8], fp32 accumulate.
__device__ __forceinline__ void mma_f16(float* c, const uint32_t* a, const uint32_t* b) {
    asm volatile(
        "mma.sync.aligned.m16n8k16.row.col.f32.f16.f16.f32 "
        "{%0,%1,%2,%3}, {%4,%5,%6,%7}, {%8,%9}, {%0,%1,%2,%3};"
        : "+f"(c[0]), "+f"(c[1]), "+f"(c[2]), "+f"(c[3])
        : "r"(a[0]), "r"(a[1]), "r"(a[2]), "r"(a[3]), "r"(b[0]), "r"(b[1]));
}

// transposed 8x8 b16 matrix pair load (B operand of m16n8k16 from [k][n] smem)
__device__ __forceinline__ void ldsm_x2_trans(uint32_t* r, uint32_t addr) {
    asm volatile("ldmatrix.sync.aligned.m8n8.x2.trans.shared.b16 {%0,%1}, [%2];"
                 : "=r"(r[0]), "=r"(r[1]) : "r"(addr));
}

__device__ __forceinline__ uint32_t packh2(float a, float b) {
    __half2 h = __floats2half2_rn(a, b);
    return *(uint32_t*)&h;
}

// exp via deg-5 Taylor (FMA pipe). |x| <~ 0.3 by construction -> err ~1e-6.
__device__ __forceinline__ float exp_small(float x) {
    float p = fmaf(x, 1.f/120.f, 1.f/24.f);
    p = fmaf(p, x, 1.f/6.f);
    p = fmaf(p, x, 0.5f);
    p = fmaf(p, x, 1.0f);
    p = fmaf(p, x, 1.0f);
    return p;
}

__device__ __forceinline__ float blockSum256(float v, float* s) {
    int lane = threadIdx.x & 31, w = threadIdx.x >> 5;
    #pragma unroll
    for (int o = 16; o; o >>= 1) v += __shfl_down_sync(0xffffffffu, v, o);
    if (!lane) s[w] = v;
    __syncthreads();
    if (threadIdx.x == 0) {
        float t = 0.f;
        #pragma unroll
        for (int i = 0; i < 8; i++) t += s[i];
        s[8] = t;
    }
    __syncthreads();
    float r = s[8];
    __syncthreads();
    return r;
}

// ---------------- weight transpose fp32[K,N] -> fp16[N,K] --------------------
__global__ void wtrans_kernel(const float* __restrict__ W, __half* __restrict__ Wt,
                              int K, int N)
{
    __shared__ float t[32][33];
    const int n0 = blockIdx.x * 32, k0 = blockIdx.y * 32;
    const int tx = threadIdx.x, ty = threadIdx.y;   // 32 x 8
    #pragma unroll
    for (int i = 0; i < 4; i++)
        t[ty + 8*i][tx] = W[(size_t)(k0 + ty + 8*i) * N + n0 + tx];
    __syncthreads();
    #pragma unroll
    for (int i = 0; i < 4; i++)
        Wt[(size_t)(n0 + ty + 8*i) * K + k0 + tx] = __float2half(t[tx][ty + 8*i]);
}

// ---------------- V per-tile column sums + suffix scan ----------------------
__global__ void vtile_kernel(const __half* __restrict__ qkv)
{
    const int b = blockIdx.x >> 5, kt = blockIdx.x & 31;
    const int k0 = kt * 64;
    float s[4] = {0.f, 0.f, 0.f, 0.f};
    const __half* vg = qkv + ((size_t)(b * SEQ + k0)) * D3 + 2 * DIM;
    for (int r = 0; r < 64; r++) {
        const __half* row = vg + (size_t)r * D3;
        #pragma unroll
        for (int l = 0; l < 4; l++) s[l] += __half2float(row[threadIdx.x + l * 256]);
    }
    float* o = g_vtile + ((size_t)(b * NTILE + kt)) * DIM;
    #pragma unroll
    for (int l = 0; l < 4; l++) o[threadIdx.x + l * 256] = s[l];
}

__global__ void vsuf_kernel()
{
    const int b = blockIdx.x;
    const int d = threadIdx.x;
    float acc = 0.f;
    g_vsuf[((size_t)b * (NTILE + 1) + NTILE) * DIM + d] = 0.f;
    for (int t = NTILE - 1; t >= 0; t--) {
        acc += g_vtile[((size_t)b * NTILE + t) * DIM + d];
        g_vsuf[((size_t)b * (NTILE + 1) + t) * DIM + d] = acc;
    }
}

// ---------------- LayerNorm (fp32 in, fp16 out) ----------
__global__ void ln_kernel(const float* __restrict__ x, const float* __restrict__ w,
                          const float* __restrict__ b, __half* __restrict__ y)
{
    __shared__ float red[9];
    const int row = blockIdx.x;
    const float* xr = x + (size_t)row * DIM;
    float v[4];
    #pragma unroll
    for (int l = 0; l < 4; l++) v[l] = xr[threadIdx.x + l * 256];
    float s = v[0] + v[1] + v[2] + v[3];
    const float mean = blockSum256(s, red) * (1.0f / DIM);
    float q = 0.f;
    #pragma unroll
    for (int l = 0; l < 4; l++) { float d = v[l] - mean; q += d * d; }
    const float ssq = blockSum256(q, red);
    const float stdv = sqrtf(ssq * (1.0f / (DIM - 1)));
    const float inv = 1.0f / (stdv + 1e-5f);
    __half* yr = y + (size_t)row * DIM;
    #pragma unroll
    for (int l = 0; l < 4; l++) {
        int c = threadIdx.x + l * 256;
        yr[c] = __float2half(w[c] * (v[l] - mean) * inv + b[c]);
    }
}

// ---------------- fp16 tensor-core GEMM (R12-proven structure) ---------------
// C[M,N] = A[M,K](half) @ Wt[N,K](half)^T + bias (+gelu)(+residual)
// BM=BN=128, BK=64, 256 threads = 8 warps; warp tile 64x32 (4x4 m16n8k16).
__global__ void __launch_bounds__(256, 2)
gemm_f16_kernel(const __half* __restrict__ A, const __half* __restrict__ Wt,
                const float* __restrict__ bias, const float* __restrict__ R,
                void* __restrict__ C, int M, int N, int K,
                int doGelu, int outHalf)
{
    extern __shared__ __half sh[];
    __half* smA = sh;                // [2][128][GST]
    __half* smB = sh + 2 * GTILE;    // [2][128][GST]

    const int tid  = threadIdx.x;
    const int lane = tid & 31, wid = tid >> 5;
    const int gid  = lane >> 2, ctg = lane & 3;
    const int wm0  = (wid >> 2) * 64;
    const int wn0  = (wid & 3) * 32;
    const int m0 = blockIdx.y << 7, n0 = blockIdx.x << 7;

    float acc[4][4][4];
    #pragma unroll
    for (int mt = 0; mt < 4; mt++)
        #pragma unroll
        for (int nt = 0; nt < 4; nt++)
            #pragma unroll
            for (int r = 0; r < 4; r++) acc[mt][nt][r] = 0.f;

    const int NC = K >> 6;

    auto loadChunk = [&](int ch, int buf) {
        const __half* Ag = A  + (size_t)m0 * K + ch * 64;
        const __half* Bg = Wt + (size_t)n0 * K + ch * 64;
        __half* Ad = smA + buf * GTILE;
        __half* Bd = smB + buf * GTILE;
        #pragma unroll
        for (int i = 0; i < 4; i++) {
            int g = tid + i * 256;               // 1024 16B-chunks per tile
            int row = g >> 3, c = g & 7;
            __pipeline_memcpy_async(Ad + row * GST + c * 8,
                                    Ag + (size_t)row * K + c * 8, 16);
            __pipeline_memcpy_async(Bd + row * GST + c * 8,
                                    Bg + (size_t)row * K + c * 8, 16);
        }
        __pipeline_commit();
    };

    loadChunk(0, 0);
    for (int it = 0; it < NC; it++) {
        if (it + 1 < NC) loadChunk(it + 1, (it + 1) & 1);
        else __pipeline_commit();
        __pipeline_wait_prior(1);
        __syncthreads();

        const __half* Ab = smA + (it & 1) * GTILE;
        const __half* Bb = smB + (it & 1) * GTILE;
        #pragma unroll
        for (int ks = 0; ks < 4; ks++) {
            const int kb = ks << 4;
            uint32_t af[4][4];
            #pragma unroll
            for (int mt = 0; mt < 4; mt++) {
                const __half* p = Ab + (wm0 + mt * 16 + gid) * GST + kb + 2 * ctg;
                af[mt][0] = *(const uint32_t*)(p);
                af[mt][1] = *(const uint32_t*)(p + 8 * GST);
                af[mt][2] = *(const uint32_t*)(p + 8);
                af[mt][3] = *(const uint32_t*)(p + 8 * GST + 8);
            }
            uint32_t bf[4][2];
            #pragma unroll
            for (int nt = 0; nt < 4; nt++) {
                const __half* p = Bb + (wn0 + nt * 8 + gid) * GST + kb + 2 * ctg;
                bf[nt][0] = *(const uint32_t*)(p);
                bf[nt][1] = *(const uint32_t*)(p + 8);
            }
            #pragma unroll
            for (int mt = 0; mt < 4; mt++)
                #pragma unroll
                for (int nt = 0; nt < 4; nt++)
                    mma_f16(acc[mt][nt], af[mt], bf[nt]);
        }
        __syncthreads();
    }

    // ---- epilogue (C fragment: rows gid/gid+8, cols 2ctg/2ctg+1) ----
    #pragma unroll
    for (int mt = 0; mt < 4; mt++) {
        #pragma unroll
        for (int half_ = 0; half_ < 2; half_++) {
            const int row = m0 + wm0 + mt * 16 + gid + half_ * 8;
            #pragma unroll
            for (int nt = 0; nt < 4; nt++) {
                const int col = n0 + wn0 + nt * 8 + 2 * ctg;
                float v0 = acc[mt][nt][half_ * 2 + 0] + bias[col];
                float v1 = acc[mt][nt][half_ * 2 + 1] + bias[col + 1];
                if (doGelu) {
                    float u = v0;
                    v0 = 0.5f * u * (1.0f + tanhf(0.7978845608028654f * (u + 0.044715f * u * u * u)));
                    u = v1;
                    v1 = 0.5f * u * (1.0f + tanhf(0.7978845608028654f * (u + 0.044715f * u * u * u)));
                }
                if (R) {
                    float2 rv = *(const float2*)(R + (size_t)row * N + col);
                    v0 += rv.x; v1 += rv.y;
                }
                if (outHalf) {
                    *(__half2*)((__half*)C + (size_t)row * N + col) =
                        __floats2half2_rn(v0, v1);
                } else {
                    float2 o; o.x = v0; o.y = v1;
                    *(float2*)((float*)C + (size_t)row * N + col) = o;
                }
            }
        }
    }
}

// ---------------- fp16 tensor-core attention ---------------------------------
// Q-tile 128 rows, K-tile 64 keys, 8 warps. Register-resident P.
// cp.async double-buffered K/V (56KB smem -> still 2 CTAs/SM).
__global__ void __launch_bounds__(256, 2)
attn_f16_kernel(const __half* __restrict__ qkv, const int* __restrict__ rel,
                const float* __restrict__ rel_emb, __half* __restrict__ out)
{
    extern __shared__ __half smh[];
    __half* Qs = smh;                   // [128][QSH]
    __half* Ks = Qs + 128 * QSH;        // [2][64][KSH]
    __half* Vs = Ks + 2 * 64 * KSH;     // [2][64][VSH]
    float*  rE = (float*)(Vs + 2 * 64 * VSH);    // [64] pre-scaled 0.125*emb
    float*  cs = rE + 64;                        // [64]

    const int b = blockIdx.x >> 4, h = blockIdx.x & 15;
    const int qt = (int)gridDim.y - 1 - (int)blockIdx.y;   // heavy blocks first
    const int q0 = qt * 128;
    const int tid = threadIdx.x;
    const int lane = tid & 31, wid = tid >> 5;
    const int gid = lane >> 2, ctg = lane & 3;
    const int wrow = wid * 16;
    const uint32_t vb0 = smem_u32(Vs);
    const uint32_t vb1 = smem_u32(Vs + 64 * VSH);

    const int nTA = 2 * qt + 2;
    const int nB  = NTILE - nTA;

    if (tid < 64) {
        rE[tid] = 0.125f * rel_emb[tid * NHEAD + h];
        cs[tid] = g_vsuf[((size_t)b * (NTILE + 1) + nTA) * DIM + h * HDIM + tid];
    }

    // load Q tile [128][64] halves
    {
        const __half* baseQ = qkv + ((size_t)(b * SEQ + q0)) * D3 + h * HDIM;
        #pragma unroll
        for (int l = 0; l < 4; l++) {
            int e = tid + l * 256;
            int row = e >> 3, c = e & 7;
            *(float4*)(Qs + row * QSH + c * 8) =
                *(const float4*)(baseQ + (size_t)row * D3 + c * 8);
        }
    }

    // cp.async K/V tile loader (2 chunks K + 2 chunks V per thread)
    auto loadKV = [&](int kt, int buf) {
        const __half* baseK = qkv + ((size_t)(b * SEQ + kt * 64)) * D3 + DIM + h * HDIM;
        __half* Kd = Ks + buf * 64 * KSH;
        __half* Vd = Vs + buf * 64 * VSH;
        #pragma unroll
        for (int l = 0; l < 2; l++) {
            int e = tid + l * 256;
            int row = e >> 3, c = e & 7;
            __pipeline_memcpy_async(Kd + row * KSH + c * 8,
                                    baseK + (size_t)row * D3 + c * 8, 16);
            __pipeline_memcpy_async(Vd + row * VSH + c * 8,
                                    baseK + DIM + (size_t)row * D3 + c * 8, 16);
        }
        __pipeline_commit();
    };

    float o[8][4];
    #pragma unroll
    for (int nt = 0; nt < 8; nt++)
        #pragma unroll
        for (int r = 0; r < 4; r++) o[nt][r] = 0.f;
    float dacc0 = 0.f, dacc1 = 0.f;

    const int qg0 = q0 + wrow + gid, qg1 = qg0 + 8;
    const int* relr0 = rel + ((size_t)b * SEQ + qg0) * SEQ;
    const int* relr1 = rel + ((size_t)b * SEQ + qg1) * SEQ;

    loadKV(0, 0);
    for (int kt = 0; kt < nTA; kt++) {
        const int k0 = kt * 64;
        const int buf = kt & 1;
        if (kt + 1 < nTA) loadKV(kt + 1, buf ^ 1);
        else __pipeline_commit();
        __pipeline_wait_prior(1);
        __syncthreads();

        const __half* Kb = Ks + buf * 64 * KSH;
        const uint32_t vb = buf ? vb1 : vb0;

        // S = Q K^T  (fp16, 4 k16 steps; scalar frag loads)
        float s[8][4];
        #pragma unroll
        for (int nt = 0; nt < 8; nt++)
            #pragma unroll
            for (int r = 0; r < 4; r++) s[nt][r] = 0.f;
        #pragma unroll
        for (int ks = 0; ks < 4; ks++) {
            const int kb = ks << 4;
            uint32_t a[4];
            const __half* ap = Qs + (wrow + gid) * QSH + kb + 2 * ctg;
            a[0] = *(const uint32_t*)(ap);
            a[1] = *(const uint32_t*)(ap + 8 * QSH);
            a[2] = *(const uint32_t*)(ap + 8);
            a[3] = *(const uint32_t*)(ap + 8 * QSH + 8);
            #pragma unroll
            for (int nt = 0; nt < 8; nt++) {
                uint32_t bb[2];
                const __half* bp = Kb + (nt * 8 + gid) * KSH + kb + 2 * ctg;
                bb[0] = *(const uint32_t*)(bp);
                bb[1] = *(const uint32_t*)(bp + 8);
                mma_f16(s[nt], a, bb);
            }
        }

        // p = exp(s * rE[rel]) for k<=q else 1 (rE pre-scaled by 0.125)
        #pragma unroll
        for (int nt = 0; nt < 8; nt++) {
            const int kg = k0 + nt * 8 + 2 * ctg;
            int2 r0 = *(const int2*)(relr0 + kg);
            int2 r1 = *(const int2*)(relr1 + kg);
            float p00 = (kg     <= qg0) ? exp_small(s[nt][0] * rE[r0.x]) : 1.0f;
            float p01 = (kg + 1 <= qg0) ? exp_small(s[nt][1] * rE[r0.y]) : 1.0f;
            float p10 = (kg     <= qg1) ? exp_small(s[nt][2] * rE[r1.x]) : 1.0f;
            float p11 = (kg + 1 <= qg1) ? exp_small(s[nt][3] * rE[r1.y]) : 1.0f;
            dacc0 += p00 + p01;
            dacc1 += p10 + p11;
            s[nt][0] = p00; s[nt][1] = p01; s[nt][2] = p10; s[nt][3] = p11;
        }

        // O += P V ; A-frags packed straight from registers
        #pragma unroll
        for (int ks = 0; ks < 4; ks++) {
            const int kb = ks << 4;
            uint32_t a[4];
            a[0] = packh2(s[2*ks][0],   s[2*ks][1]);
            a[1] = packh2(s[2*ks][2],   s[2*ks][3]);
            a[2] = packh2(s[2*ks+1][0], s[2*ks+1][1]);
            a[3] = packh2(s[2*ks+1][2], s[2*ks+1][3]);
            const uint32_t vrow = vb + (uint32_t)(((kb + (lane & 15)) * VSH) * 2);
            #pragma unroll
            for (int nt = 0; nt < 8; nt++) {
                uint32_t bb[2];
                ldsm_x2_trans(bb, vrow + nt * 16);
                mma_f16(o[nt], a, bb);
            }
        }
        __syncthreads();   // all warps done with buf before it is reloaded
    }

    // row denominators: reduce dacc over the 4 ctg lanes, add masked count
    dacc0 += __shfl_xor_sync(0xffffffffu, dacc0, 1);
    dacc0 += __shfl_xor_sync(0xffffffffu, dacc0, 2);
    dacc1 += __shfl_xor_sync(0xffffffffu, dacc1, 1);
    dacc1 += __shfl_xor_sync(0xffffffffu, dacc1, 2);
    const float i0 = 1.0f / (dacc0 + 64.0f * (float)nB);
    const float i1 = 1.0f / (dacc1 + 64.0f * (float)nB);

    __half* o0 = out + ((size_t)b * SEQ + qg0) * DIM + h * HDIM;
    __half* o1 = out + ((size_t)b * SEQ + qg1) * DIM + h * HDIM;
    #pragma unroll
    for (int nt = 0; nt < 8; nt++) {
        const int c = nt * 8 + 2 * ctg;
        const float cs0 = cs[c], cs1 = cs[c + 1];
        *(__half2*)(o0 + c) = __floats2half2_rn((o[nt][0] + cs0) * i0,
                                                (o[nt][1] + cs1) * i0);
        *(__half2*)(o1 + c) = __floats2half2_rn((o[nt][2] + cs0) * i1,
                                                (o[nt][3] + cs1) * i1);
    }
}

// ---------------- launcher ----------------
extern "C" void kernel_launch(void* const* d_in, const int* in_sizes, int n_in,
                              void* d_out, int out_size)
{
    const float* x     = (const float*)d_in[0];
    const int*   rel   = (const int*)  d_in[1];
    const float* ln1w  = (const float*)d_in[2];
    const float* ln1b  = (const float*)d_in[3];
    const float* Wqkv  = (const float*)d_in[4];
    const float* bqkv  = (const float*)d_in[5];
    const float* Wo    = (const float*)d_in[6];
    const float* bo    = (const float*)d_in[7];
    const float* rele  = (const float*)d_in[8];
    const float* ln2w  = (const float*)d_in[9];
    const float* ln2b  = (const float*)d_in[10];
    const float* Wfc   = (const float*)d_in[11];
    const float* bfc   = (const float*)d_in[12];
    const float* Wp    = (const float*)d_in[13];
    const float* bp    = (const float*)d_in[14];
    float* out = (float*)d_out;

    __half *h1, *qkv, *attnh, *h2, *fc, *wq, *wo, *wf, *wp;
    float *x1;
    cudaGetSymbolAddress((void**)&h1,    g_h1);
    cudaGetSymbolAddress((void**)&qkv,   g_qkv);
    cudaGetSymbolAddress((void**)&attnh, g_attn);
    cudaGetSymbolAddress((void**)&x1,    g_x1);
    cudaGetSymbolAddress((void**)&h2,    g_h2);
    cudaGetSymbolAddress((void**)&fc,    g_fc);
    cudaGetSymbolAddress((void**)&wq,    g_wq);
    cudaGetSymbolAddress((void**)&wo,    g_wo);
    cudaGetSymbolAddress((void**)&wf,    g_wf);
    cudaGetSymbolAddress((void**)&wp,    g_wp);

    const int gemmSmem = 4 * GTILE * (int)sizeof(__half);   // 73728 B
    cudaFuncSetAttribute(gemm_f16_kernel,
                         cudaFuncAttributeMaxDynamicSharedMemorySize, gemmSmem);
    const int attnSmem = (128*QSH + 2*64*KSH + 2*64*VSH) * (int)sizeof(__half)
                         + 128 * (int)sizeof(float);        // 55808 B
    cudaFuncSetAttribute(attn_f16_kernel,
                         cudaFuncAttributeMaxDynamicSharedMemorySize, attnSmem);

    // 0. transpose + fp16-convert weights: Wt[N][K]
    {
        dim3 blk(32, 8);
        wtrans_kernel<<<dim3(D3/32,  DIM/32), blk>>>(Wqkv, wq, DIM, D3);
        wtrans_kernel<<<dim3(DIM/32, DIM/32), blk>>>(Wo,   wo, DIM, DIM);
        wtrans_kernel<<<dim3(D4/32,  DIM/32), blk>>>(Wfc,  wf, DIM, D4);
        wtrans_kernel<<<dim3(DIM/32, D4/32),  blk>>>(Wp,   wp, D4,  DIM);
    }

    // 1. LN1 -> h1 (fp16)
    ln_kernel<<<ROWS, 256>>>(x, ln1w, ln1b, h1);
    // 2. QKV GEMM -> qkv (fp16)
    gemm_f16_kernel<<<dim3(D3/128, ROWS/128), 256, gemmSmem>>>(
        h1, wq, bqkv, nullptr, qkv, ROWS, D3, DIM, 0, 1);
    // 2b. V colsums + suffix scan
    vtile_kernel<<<BATCH*NTILE, 256>>>(qkv);
    vsuf_kernel<<<BATCH, 1024>>>();
    // 3. Attention -> attnh (fp16)
    attn_f16_kernel<<<dim3(BATCH*NHEAD, SEQ/128), 256, attnSmem>>>(qkv, rel, rele, attnh);
    // 4. Wo + residual(x) -> x1 (fp32)
    gemm_f16_kernel<<<dim3(DIM/128, ROWS/128), 256, gemmSmem>>>(
        attnh, wo, bo, x, x1, ROWS, DIM, DIM, 0, 0);
    // 5. LN2 -> h2 (fp16)
    ln_kernel<<<ROWS, 256>>>(x1, ln2w, ln2b, h2);
    // 6. FC + GELU -> fc (fp16)
    gemm_f16_kernel<<<dim3(D4/128, ROWS/128), 256, gemmSmem>>>(
        h2, wf, bfc, nullptr, fc, ROWS, D4, DIM, 1, 1);
    // 7. Wp + residual(x1) -> out (fp32)
    gemm_f16_kernel<<<dim3(DIM/128, ROWS/128), 256, gemmSmem>>>(
        fc, wp, bp, x1, out, ROWS, DIM, D4, 0, 0);
}